// round 14
// baseline (speedup 1.0000x reference)
#include <cuda_runtime.h>
#include <math.h>

#define NB 8
#define NC 64
#define NS 256
#define NM 32
#define HW (NS*NS)

typedef unsigned long long u64;
typedef unsigned int u32;

__device__ __forceinline__ u32 tf32b(float f) {
    u32 u; asm("cvt.rna.tf32.f32 %0, %1;" : "=r"(u) : "f"(f)); return u;
}
__device__ __forceinline__ float stf(float f) { return __uint_as_float(tf32b(f)); }
__device__ __forceinline__ void mma816(float* d, const u32* a, const u32* b) {
    asm volatile("mma.sync.aligned.m16n8k8.row.col.f32.tf32.tf32.f32 "
        "{%0,%1,%2,%3}, {%4,%5,%6,%7}, {%8,%9}, {%0,%1,%2,%3};"
        : "+f"(d[0]), "+f"(d[1]), "+f"(d[2]), "+f"(d[3])
        : "r"(a[0]), "r"(a[1]), "r"(a[2]), "r"(a[3]), "r"(b[0]), "r"(b[1]));
}

// ---------------- static device scratch ----------------
__device__ float g_basisT[64*NS];      // fwd DFT [ko][t] tf32-rounded
__device__ float g_ibasis[NS*64];      // inv DFT [t][ko] tf32-rounded
__device__ float g_ibasisT[64*NS];     // inv DFT [ko][t] tf32-rounded
__device__ float g_whA[2][NM*NC*NC];   // [re/im][k][o][i] tf32-rounded
__device__ float g_wwA[2][NM*NC*NC];
__device__ float g_w1t[8192];          // fc1w tf32 [c][j]
__device__ float g_w2t[8192];          // fc2w tf32 [j][o]
__device__ float g_Xh[(size_t)NB*NC*64*NS];
__device__ float g_Xw[(size_t)NB*NC*64*NS];
__device__ float g_Oh[(size_t)NB*NC*64*NS];
__device__ float g_Ow[(size_t)NB*NC*64*NS];
__device__ float g_f [(size_t)NB*NC*HW];

// ---------------- init ----------------
__global__ void initK(const float* __restrict__ whr, const float* __restrict__ whi,
                      const float* __restrict__ wwr, const float* __restrict__ wwi,
                      const float* __restrict__ fc1w, const float* __restrict__ fc2w) {
    int idx = blockIdx.x * 256 + threadIdx.x;      // covers 131072
    if (idx < NS*64) {
        int t = idx >> 6, ko = idx & 63, k = ko >> 1;
        float s, c;
        sincospif((float)((k * t) & 255) / 128.0f, &s, &c);
        g_basisT[ko*NS + t] = stf((ko & 1) ? -s : c);
        float a = (k == 0) ? (1.0f/NS) : (2.0f/NS);
        float iv = (ko & 1) ? ((k == 0) ? 0.0f : -a*s) : a*c;
        g_ibasis[t*64 + ko]  = stf(iv);
        g_ibasisT[ko*NS + t] = stf(iv);
    }
    if (idx < NM*NC*NC) {
        int k = idx >> 12, r = idx & 4095, o = r >> 6, i = r & 63;
        int src = (i*NC + o)*NM + k;
        g_whA[0][idx] = stf(whr[src]);  g_whA[1][idx] = stf(whi[src]);
        g_wwA[0][idx] = stf(wwr[src]);  g_wwA[1][idx] = stf(wwi[src]);
    }
    if (idx < 8192) {
        g_w1t[idx] = stf(fc1w[idx]);
        g_w2t[idx] = stf(fc2w[idx]);
    }
}

// ---------------- forward DFT over H: Xh[ko][w] = basisT[ko][h] @ x[h][w] ----------------
// smem: sA 64*68 (17408) | sB 64*136 (34816) => 52224
#define FDH_SMEM 52224
__global__ void __launch_bounds__(256, 3) fdftHm(const float* __restrict__ x) {
    extern __shared__ __align__(16) char smem[];
    float* sA = (float*)smem;
    float* sB = (float*)(smem + 17408);
    int slab = blockIdx.x;
    int w0 = blockIdx.y * 128;
    const float* xp = x + (size_t)slab * HW;
    int tid = threadIdx.x, lane = tid & 31, w = tid >> 5;
    int g = lane >> 2, tig = lane & 3;
    int warpM = w & 1, warpN = w >> 1;     // 2 x 4
    float acc[2][4][4] = {};
    for (int hc = 0; hc < NS; hc += 64) {
        for (int idx = tid; idx < 4096; idx += 256) {
            int ko = idx >> 6, hh = idx & 63;
            sA[ko*68 + hh] = g_basisT[ko*NS + hc + hh];
        }
        for (int idx = tid; idx < 8192; idx += 256) {
            int hh = idx >> 7, ww = idx & 127;
            sB[hh*136 + ww] = stf(xp[(size_t)(hc + hh)*NS + w0 + ww]);
        }
        __syncthreads();
        #pragma unroll
        for (int ks = 0; ks < 8; ks++) {
            int k0 = ks * 8;
            u32 af[2][4];
            #pragma unroll
            for (int mt = 0; mt < 2; mt++) {
                int r0 = warpM*32 + mt*16;
                af[mt][0] = __float_as_uint(sA[(r0+g)*68 + k0 + tig]);
                af[mt][1] = __float_as_uint(sA[(r0+g+8)*68 + k0 + tig]);
                af[mt][2] = __float_as_uint(sA[(r0+g)*68 + k0 + tig + 4]);
                af[mt][3] = __float_as_uint(sA[(r0+g+8)*68 + k0 + tig + 4]);
            }
            #pragma unroll
            for (int nt = 0; nt < 4; nt++) {
                int n0 = warpN*32 + nt*8;
                u32 bf[2];
                bf[0] = __float_as_uint(sB[(k0+tig)*136 + n0 + g]);
                bf[1] = __float_as_uint(sB[(k0+tig+4)*136 + n0 + g]);
                mma816(acc[0][nt], af[0], bf);
                mma816(acc[1][nt], af[1], bf);
            }
        }
        __syncthreads();
    }
    float* dst = g_Xh + (size_t)slab * 64 * NS;
    #pragma unroll
    for (int mt = 0; mt < 2; mt++) {
        int row = warpM*32 + mt*16 + g;
        #pragma unroll
        for (int nt = 0; nt < 4; nt++) {
            int col = w0 + warpN*32 + nt*8 + 2*tig;
            *(float2*)&dst[row*NS + col]     = make_float2(acc[mt][nt][0], acc[mt][nt][1]);
            *(float2*)&dst[(row+8)*NS + col] = make_float2(acc[mt][nt][2], acc[mt][nt][3]);
        }
    }
}

// ---------------- forward DFT over W: Xw[ko][h] = basisT[ko][w] @ xT[w][h] ----------------
// smem: sA 64*68 (17408) | sB 64*133 (34048) => 51456
#define FDW_SMEM 51456
__global__ void __launch_bounds__(256, 3) fdftWm(const float* __restrict__ x) {
    extern __shared__ __align__(16) char smem[];
    float* sA = (float*)smem;
    float* sB = (float*)(smem + 17408);
    int slab = blockIdx.x;
    int h0 = blockIdx.y * 128;
    const float* xp = x + (size_t)slab * HW;
    int tid = threadIdx.x, lane = tid & 31, w = tid >> 5;
    int g = lane >> 2, tig = lane & 3;
    int warpM = w & 1, warpN = w >> 1;
    float acc[2][4][4] = {};
    for (int wc = 0; wc < NS; wc += 64) {
        for (int idx = tid; idx < 4096; idx += 256) {
            int ko = idx >> 6, ww = idx & 63;
            sA[ko*68 + ww] = g_basisT[ko*NS + wc + ww];
        }
        for (int idx = tid; idx < 8192; idx += 256) {
            int hh = idx >> 6, ww = idx & 63;
            sB[ww*133 + hh] = stf(xp[(size_t)(h0 + hh)*NS + wc + ww]);
        }
        __syncthreads();
        #pragma unroll
        for (int ks = 0; ks < 8; ks++) {
            int k0 = ks * 8;
            u32 af[2][4];
            #pragma unroll
            for (int mt = 0; mt < 2; mt++) {
                int r0 = warpM*32 + mt*16;
                af[mt][0] = __float_as_uint(sA[(r0+g)*68 + k0 + tig]);
                af[mt][1] = __float_as_uint(sA[(r0+g+8)*68 + k0 + tig]);
                af[mt][2] = __float_as_uint(sA[(r0+g)*68 + k0 + tig + 4]);
                af[mt][3] = __float_as_uint(sA[(r0+g+8)*68 + k0 + tig + 4]);
            }
            #pragma unroll
            for (int nt = 0; nt < 4; nt++) {
                int n0 = warpN*32 + nt*8;
                u32 bf[2];
                bf[0] = __float_as_uint(sB[(k0+tig)*133 + n0 + g]);
                bf[1] = __float_as_uint(sB[(k0+tig+4)*133 + n0 + g]);
                mma816(acc[0][nt], af[0], bf);
                mma816(acc[1][nt], af[1], bf);
            }
        }
        __syncthreads();
    }
    float* dst = g_Xw + (size_t)slab * 64 * NS;
    #pragma unroll
    for (int mt = 0; mt < 2; mt++) {
        int row = warpM*32 + mt*16 + g;
        #pragma unroll
        for (int nt = 0; nt < 4; nt++) {
            int col = h0 + warpN*32 + nt*8 + 2*tig;
            *(float2*)&dst[row*NS + col]     = make_float2(acc[mt][nt][0], acc[mt][nt][1]);
            *(float2*)&dst[(row+8)*NS + col] = make_float2(acc[mt][nt][2], acc[mt][nt][3]);
        }
    }
}

// ---------------- per-mode complex mix: O = W @ X (complex), per (b,k), c0 64-wide ----------------
// smem: sWr 64*68 | sWi 64*68 | sXr 64*72 | sXi 64*72 => 71680
#define MIX_SMEM 71680
__global__ void __launch_bounds__(256, 3) mixKm() {
    extern __shared__ __align__(16) char smem[];
    float* sWr = (float*)smem;
    float* sWi = (float*)(smem + 17408);
    float* sXr = (float*)(smem + 34816);
    float* sXi = (float*)(smem + 53248);
    int br = blockIdx.z;
    const float* Xin = br ? g_Xw : g_Xh;
    const float* Wr  = br ? g_wwA[0] : g_whA[0];
    const float* Wi  = br ? g_wwA[1] : g_whA[1];
    float* Out       = br ? g_Ow : g_Oh;
    int b = blockIdx.x >> 5, k = blockIdx.x & 31;
    int c0 = blockIdx.y * 64;
    int tid = threadIdx.x, lane = tid & 31, w = tid >> 5;
    int g = lane >> 2, tig = lane & 3;
    int warpM = w & 1, warpN = w >> 1;     // 2 x 4: 32 rows x 16 cols
    for (int idx = tid; idx < 4096; idx += 256) {
        int o = idx >> 6, i = idx & 63;
        sWr[o*68 + i] = Wr[k*4096 + o*64 + i];
        sWi[o*68 + i] = Wi[k*4096 + o*64 + i];
    }
    for (int idx = tid; idx < 4096; idx += 256) {
        int i = idx >> 6, c = idx & 63;
        const float* xb = Xin + ((size_t)(b*64 + i)*64 + 2*k)*NS + c0;
        sXr[i*72 + c] = stf(xb[c]);
        sXi[i*72 + c] = stf(xb[NS + c]);
    }
    __syncthreads();
    float accR[2][2][4] = {}, accI[2][2][4] = {};
    #pragma unroll
    for (int ks = 0; ks < 8; ks++) {
        int k0 = ks * 8;
        u32 ar[2][4], ai[2][4], nai[2][4];
        #pragma unroll
        for (int mt = 0; mt < 2; mt++) {
            int r0 = warpM*32 + mt*16;
            ar[mt][0] = __float_as_uint(sWr[(r0+g)*68 + k0 + tig]);
            ar[mt][1] = __float_as_uint(sWr[(r0+g+8)*68 + k0 + tig]);
            ar[mt][2] = __float_as_uint(sWr[(r0+g)*68 + k0 + tig + 4]);
            ar[mt][3] = __float_as_uint(sWr[(r0+g+8)*68 + k0 + tig + 4]);
            ai[mt][0] = __float_as_uint(sWi[(r0+g)*68 + k0 + tig]);
            ai[mt][1] = __float_as_uint(sWi[(r0+g+8)*68 + k0 + tig]);
            ai[mt][2] = __float_as_uint(sWi[(r0+g)*68 + k0 + tig + 4]);
            ai[mt][3] = __float_as_uint(sWi[(r0+g+8)*68 + k0 + tig + 4]);
            #pragma unroll
            for (int j = 0; j < 4; j++) nai[mt][j] = ai[mt][j] ^ 0x80000000u;
        }
        #pragma unroll
        for (int nt = 0; nt < 2; nt++) {
            int n0 = warpN*16 + nt*8;
            u32 bfr[2], bfi[2];
            bfr[0] = __float_as_uint(sXr[(k0+tig)*72 + n0 + g]);
            bfr[1] = __float_as_uint(sXr[(k0+tig+4)*72 + n0 + g]);
            bfi[0] = __float_as_uint(sXi[(k0+tig)*72 + n0 + g]);
            bfi[1] = __float_as_uint(sXi[(k0+tig+4)*72 + n0 + g]);
            #pragma unroll
            for (int mt = 0; mt < 2; mt++) {
                mma816(accR[mt][nt], ar[mt], bfr);
                mma816(accR[mt][nt], nai[mt], bfi);
                mma816(accI[mt][nt], ar[mt], bfi);
                mma816(accI[mt][nt], ai[mt], bfr);
            }
        }
    }
    #pragma unroll
    for (int mt = 0; mt < 2; mt++) {
        #pragma unroll
        for (int nt = 0; nt < 2; nt++) {
            int col = c0 + warpN*16 + nt*8 + 2*tig;
            int o0 = warpM*32 + mt*16 + g;
            float* ob0 = Out + ((size_t)(b*64 + o0)*64 + 2*k)*NS + col;
            *(float2*)ob0        = make_float2(accR[mt][nt][0], accR[mt][nt][1]);
            *(float2*)(ob0 + NS) = make_float2(accI[mt][nt][0], accI[mt][nt][1]);
            float* ob1 = Out + ((size_t)(b*64 + o0 + 8)*64 + 2*k)*NS + col;
            *(float2*)ob1        = make_float2(accR[mt][nt][2], accR[mt][nt][3]);
            *(float2*)(ob1 + NS) = make_float2(accI[mt][nt][2], accI[mt][nt][3]);
        }
    }
}

// ---------------- fused inverse DFTs: f = IBh@Oh + OwT@IBw, 64x64 tiles ----------------
// smem: sAh 64*68 (17408) | sAw 64*69 (17664) | sBh 64*72 (18432) | sBw 64*72 (18432) => 71936
#define INV_SMEM 71936
__global__ void __launch_bounds__(256, 3) invHWm() {
    extern __shared__ __align__(16) char smem[];
    float* sAh = (float*)smem;
    float* sAw = (float*)(smem + 17408);
    float* sBh = (float*)(smem + 35072);
    float* sBw = (float*)(smem + 53504);
    int slab = blockIdx.x;
    int h0 = (blockIdx.y >> 2) * 64, w0 = (blockIdx.y & 3) * 64;
    const float* Oh = g_Oh + (size_t)slab * 64 * NS;
    const float* Ow = g_Ow + (size_t)slab * 64 * NS;
    int tid = threadIdx.x, lane = tid & 31, w = tid >> 5;
    int g = lane >> 2, tig = lane & 3;
    int warpM = w & 1, warpN = w >> 1;     // 2 x 4: 32 rows x 16 cols
    for (int idx = tid; idx < 4096; idx += 256) {
        int r = idx >> 6, c = idx & 63;
        sAh[r*68 + c] = g_ibasis[(h0 + r)*64 + c];
    }
    for (int idx = tid; idx < 4096; idx += 256) {
        int ko = idx >> 6, hh = idx & 63;
        sAw[hh*69 + ko] = stf(Ow[ko*NS + h0 + hh]);
    }
    for (int idx = tid; idx < 4096; idx += 256) {
        int ko = idx >> 6, ww = idx & 63;
        sBh[ko*72 + ww] = stf(Oh[ko*NS + w0 + ww]);
        sBw[ko*72 + ww] = g_ibasisT[ko*NS + w0 + ww];
    }
    __syncthreads();
    float acc[2][2][4] = {};
    #pragma unroll
    for (int ks = 0; ks < 8; ks++) {
        int k0 = ks * 8;
        u32 ah[2][4], aw[2][4];
        #pragma unroll
        for (int mt = 0; mt < 2; mt++) {
            int r0 = warpM*32 + mt*16;
            ah[mt][0] = __float_as_uint(sAh[(r0+g)*68 + k0 + tig]);
            ah[mt][1] = __float_as_uint(sAh[(r0+g+8)*68 + k0 + tig]);
            ah[mt][2] = __float_as_uint(sAh[(r0+g)*68 + k0 + tig + 4]);
            ah[mt][3] = __float_as_uint(sAh[(r0+g+8)*68 + k0 + tig + 4]);
            aw[mt][0] = __float_as_uint(sAw[(r0+g)*69 + k0 + tig]);
            aw[mt][1] = __float_as_uint(sAw[(r0+g+8)*69 + k0 + tig]);
            aw[mt][2] = __float_as_uint(sAw[(r0+g)*69 + k0 + tig + 4]);
            aw[mt][3] = __float_as_uint(sAw[(r0+g+8)*69 + k0 + tig + 4]);
        }
        #pragma unroll
        for (int nt = 0; nt < 2; nt++) {
            int n0 = warpN*16 + nt*8;
            u32 bh[2], bw[2];
            bh[0] = __float_as_uint(sBh[(k0+tig)*72 + n0 + g]);
            bh[1] = __float_as_uint(sBh[(k0+tig+4)*72 + n0 + g]);
            bw[0] = __float_as_uint(sBw[(k0+tig)*72 + n0 + g]);
            bw[1] = __float_as_uint(sBw[(k0+tig+4)*72 + n0 + g]);
            #pragma unroll
            for (int mt = 0; mt < 2; mt++) {
                mma816(acc[mt][nt], ah[mt], bh);
                mma816(acc[mt][nt], aw[mt], bw);
            }
        }
    }
    __syncthreads();   // sAh dead; reuse as output staging [64][68]
    #pragma unroll
    for (int mt = 0; mt < 2; mt++) {
        int r0 = warpM*32 + mt*16 + g;
        #pragma unroll
        for (int nt = 0; nt < 2; nt++) {
            int col = warpN*16 + nt*8 + 2*tig;
            *(float2*)&sAh[r0*68 + col]     = make_float2(acc[mt][nt][0], acc[mt][nt][1]);
            *(float2*)&sAh[(r0+8)*68 + col] = make_float2(acc[mt][nt][2], acc[mt][nt][3]);
        }
    }
    __syncthreads();
    float* fp = g_f + (size_t)slab * HW;
    for (int idx = tid; idx < 4096; idx += 256) {
        int r = idx >> 6, c = idx & 63;
        fp[(size_t)(h0 + r)*NS + w0 + c] = sAh[r*68 + c];
    }
}

// ---------------- mma.sync tf32 FFN: 128 px / block, 512 threads (unchanged from R12) ----------------
#define FFN_SMEM 141312
#define OFF_SA 2048
#define OFF_T1 36864
#define OFF_WB 104448

__global__ void __launch_bounds__(512) ffnM(const float* __restrict__ x,
        const float* __restrict__ b1, const float* __restrict__ lng,
        const float* __restrict__ lnb, const float* __restrict__ b2,
        float* __restrict__ out) {
    extern __shared__ __align__(16) char smem[];
    float* sVec = (float*)smem;
    float* sA = (float*)(smem + OFF_SA);
    float* sT = (float*)(smem + OFF_T1);
    float* sW = (float*)(smem + OFF_WB);
    int tid = threadIdx.x, lane = tid & 31, w = tid >> 5;
    int b  = blockIdx.x >> 9;
    int p0 = (blockIdx.x & 511) * 128;

    if (tid < 128) { sVec[tid] = b1[tid]; sVec[128+tid] = lng[tid]; sVec[256+tid] = lnb[tid]; }
    if (tid < 64) sVec[384+tid] = b2[tid];
    for (int i = tid; i < 2048; i += 512) {
        int c = i >> 5, j4 = (i & 31) * 4;
        *(float4*)&sW[c*136 + j4] = ((const float4*)g_w1t)[i];
    }
    for (int i = tid; i < 8192; i += 512) {
        int c = i >> 7, px = i & 127;
        sA[px*68 + c] = stf(g_f[((size_t)(b*64 + c) << 16) + p0 + px]);
    }
    __syncthreads();

    int warpM = w & 3, warpN = w >> 2;
    int g = lane >> 2, tig = lane & 3;

    float acc[2][4][4] = {};
    #pragma unroll
    for (int ks = 0; ks < 8; ks++) {
        int k0 = ks * 8;
        u32 afr[2][4];
        #pragma unroll
        for (int mt = 0; mt < 2; mt++) {
            const float* ap = sA + (warpM*32 + mt*16)*68 + k0;
            afr[mt][0] = __float_as_uint(ap[g*68 + tig]);
            afr[mt][1] = __float_as_uint(ap[(g+8)*68 + tig]);
            afr[mt][2] = __float_as_uint(ap[g*68 + tig + 4]);
            afr[mt][3] = __float_as_uint(ap[(g+8)*68 + tig + 4]);
        }
        #pragma unroll
        for (int nt = 0; nt < 4; nt++) {
            const float* bp = sW + k0*136 + warpN*32 + nt*8;
            u32 bfr[2];
            bfr[0] = __float_as_uint(bp[tig*136 + g]);
            bfr[1] = __float_as_uint(bp[(tig+4)*136 + g]);
            mma816(acc[0][nt], afr[0], bfr);
            mma816(acc[1][nt], afr[1], bfr);
        }
    }
    #pragma unroll
    for (int mt = 0; mt < 2; mt++) {
        int r0 = warpM*32 + mt*16 + g;
        #pragma unroll
        for (int nt = 0; nt < 4; nt++) {
            int cb = warpN*32 + nt*8 + 2*tig;
            float bb0 = sVec[cb], bb1 = sVec[cb+1];
            sT[r0*132 + cb]     = fmaxf(acc[mt][nt][0] + bb0, 0.f);
            sT[r0*132 + cb + 1] = fmaxf(acc[mt][nt][1] + bb1, 0.f);
            sT[(r0+8)*132 + cb]     = fmaxf(acc[mt][nt][2] + bb0, 0.f);
            sT[(r0+8)*132 + cb + 1] = fmaxf(acc[mt][nt][3] + bb1, 0.f);
        }
    }
    __syncthreads();

    for (int p8 = 0; p8 < 8; p8++) {
        int px = w*8 + p8;
        float4 v = *(float4*)&sT[px*132 + lane*4];
        float s1 = v.x + v.y + v.z + v.w;
        float s2 = v.x*v.x + v.y*v.y + v.z*v.z + v.w*v.w;
        #pragma unroll
        for (int o = 16; o > 0; o >>= 1) {
            s1 += __shfl_xor_sync(0xFFFFFFFFu, s1, o);
            s2 += __shfl_xor_sync(0xFFFFFFFFu, s2, o);
        }
        float mu  = s1 * (1.0f/128.0f);
        float var = s2 * (1.0f/128.0f) - mu*mu;
        float inv = rsqrtf(var + 1e-5f);
        float4 gm = *(float4*)&sVec[128 + lane*4];
        float4 bt = *(float4*)&sVec[256 + lane*4];
        uint4 q;
        q.x = tf32b((v.x - mu)*inv*gm.x + bt.x);
        q.y = tf32b((v.y - mu)*inv*gm.y + bt.y);
        q.z = tf32b((v.z - mu)*inv*gm.z + bt.z);
        q.w = tf32b((v.w - mu)*inv*gm.w + bt.w);
        *(uint4*)&sT[px*132 + lane*4] = q;
    }
    __syncthreads();

    for (int i = tid; i < 2048; i += 512) {
        int j = i >> 4, o4 = (i & 15) * 4;
        *(float4*)&sW[j*72 + o4] = ((const float4*)g_w2t)[i];
    }
    __syncthreads();

    float acc2[2][2][4] = {};
    #pragma unroll
    for (int ks = 0; ks < 16; ks++) {
        int k0 = ks * 8;
        u32 afr[2][4];
        #pragma unroll
        for (int mt = 0; mt < 2; mt++) {
            const float* ap = sT + (warpM*32 + mt*16)*132 + k0;
            afr[mt][0] = __float_as_uint(ap[g*132 + tig]);
            afr[mt][1] = __float_as_uint(ap[(g+8)*132 + tig]);
            afr[mt][2] = __float_as_uint(ap[g*132 + tig + 4]);
            afr[mt][3] = __float_as_uint(ap[(g+8)*132 + tig + 4]);
        }
        #pragma unroll
        for (int nt = 0; nt < 2; nt++) {
            const float* bp = sW + k0*72 + warpN*16 + nt*8;
            u32 bfr[2];
            bfr[0] = __float_as_uint(bp[tig*72 + g]);
            bfr[1] = __float_as_uint(bp[(tig+4)*72 + g]);
            mma816(acc2[0][nt], afr[0], bfr);
            mma816(acc2[1][nt], afr[1], bfr);
        }
    }
    __syncthreads();
    float* sO = sA;
    #pragma unroll
    for (int mt = 0; mt < 2; mt++) {
        int r0 = warpM*32 + mt*16 + g;
        #pragma unroll
        for (int nt = 0; nt < 2; nt++) {
            int ob = warpN*16 + nt*8 + 2*tig;
            float bb0 = sVec[384 + ob], bb1 = sVec[384 + ob + 1];
            sO[ob*132 + r0]       = acc2[mt][nt][0] + bb0;
            sO[(ob+1)*132 + r0]   = acc2[mt][nt][1] + bb1;
            sO[ob*132 + r0 + 8]   = acc2[mt][nt][2] + bb0;
            sO[(ob+1)*132 + r0+8] = acc2[mt][nt][3] + bb1;
        }
    }
    __syncthreads();
    for (int i = tid; i < 8192; i += 512) {
        int o = i >> 7, px = i & 127;
        size_t gg = ((size_t)(b*64 + o) << 16) + p0 + px;
        out[gg] = sO[o*132 + px] + x[gg];
    }
}

// ---------------- launch ----------------
extern "C" void kernel_launch(void* const* d_in, const int* in_sizes, int n_in,
                              void* d_out, int out_size) {
    const float* x    = (const float*)d_in[0];
    const float* whr  = (const float*)d_in[1];
    const float* whi  = (const float*)d_in[2];
    const float* wwr  = (const float*)d_in[3];
    const float* wwi  = (const float*)d_in[4];
    const float* fc1w = (const float*)d_in[5];
    const float* fc1b = (const float*)d_in[6];
    const float* lng  = (const float*)d_in[7];
    const float* lnb  = (const float*)d_in[8];
    const float* fc2w = (const float*)d_in[9];
    const float* fc2b = (const float*)d_in[10];
    float* out = (float*)d_out;

    cudaFuncSetAttribute(fdftHm, cudaFuncAttributeMaxDynamicSharedMemorySize, FDH_SMEM);
    cudaFuncSetAttribute(fdftWm, cudaFuncAttributeMaxDynamicSharedMemorySize, FDW_SMEM);
    cudaFuncSetAttribute(mixKm,  cudaFuncAttributeMaxDynamicSharedMemorySize, MIX_SMEM);
    cudaFuncSetAttribute(invHWm, cudaFuncAttributeMaxDynamicSharedMemorySize, INV_SMEM);
    cudaFuncSetAttribute(ffnM,   cudaFuncAttributeMaxDynamicSharedMemorySize, FFN_SMEM);

    initK<<<512, 256>>>(whr, whi, wwr, wwi, fc1w, fc2w);
    fdftHm<<<dim3(512, 2), 256, FDH_SMEM>>>(x);
    fdftWm<<<dim3(512, 2), 256, FDW_SMEM>>>(x);
    mixKm<<<dim3(256, 4, 2), 256, MIX_SMEM>>>();
    invHWm<<<dim3(512, 16), 256, INV_SMEM>>>();
    ffnM<<<4096, 512, FFN_SMEM>>>(x, fc1b, lng, lnb, fc2b, out);
}

// round 15
// speedup vs baseline: 1.1446x; 1.1446x over previous
#include <cuda_runtime.h>
#include <math.h>

#define NB 8
#define NC 64
#define NS 256
#define NM 32
#define HW (NS*NS)

typedef unsigned long long u64;
typedef unsigned int u32;

__device__ __forceinline__ u32 tf32b(float f) {
    u32 u; asm("cvt.rna.tf32.f32 %0, %1;" : "=r"(u) : "f"(f)); return u;
}
__device__ __forceinline__ float stf(float f) { return __uint_as_float(tf32b(f)); }
__device__ __forceinline__ void mma816(float* d, const u32* a, const u32* b) {
    asm volatile("mma.sync.aligned.m16n8k8.row.col.f32.tf32.tf32.f32 "
        "{%0,%1,%2,%3}, {%4,%5,%6,%7}, {%8,%9}, {%0,%1,%2,%3};"
        : "+f"(d[0]), "+f"(d[1]), "+f"(d[2]), "+f"(d[3])
        : "r"(a[0]), "r"(a[1]), "r"(a[2]), "r"(a[3]), "r"(b[0]), "r"(b[1]));
}

// ---------------- static device scratch ----------------
__device__ float g_basisT[64*NS];      // fwd DFT [ko][t] tf32-rounded
__device__ float g_ibasis[NS*64];      // inv DFT [t][ko] tf32-rounded
__device__ float g_ibasisT[64*NS];     // inv DFT [ko][t] tf32-rounded
__device__ float g_whA[2][NM*NC*NC];   // [re/im][k][o][i] tf32-rounded
__device__ float g_wwA[2][NM*NC*NC];
__device__ float g_w1t[8192];          // fc1w tf32 [c][j]
__device__ float g_w2t[8192];          // fc2w tf32 [j][o]
__device__ float g_Xh[(size_t)NB*NC*64*NS];
__device__ float g_Xw[(size_t)NB*NC*64*NS];
__device__ float g_Oh[(size_t)NB*NC*64*NS];
__device__ float g_Ow[(size_t)NB*NC*64*NS];
__device__ float g_f [(size_t)NB*NC*HW];

// ---------------- init ----------------
__global__ void initK(const float* __restrict__ whr, const float* __restrict__ whi,
                      const float* __restrict__ wwr, const float* __restrict__ wwi,
                      const float* __restrict__ fc1w, const float* __restrict__ fc2w) {
    int idx = blockIdx.x * 256 + threadIdx.x;      // covers 131072
    if (idx < NS*64) {
        int t = idx >> 6, ko = idx & 63, k = ko >> 1;
        float s, c;
        sincospif((float)((k * t) & 255) / 128.0f, &s, &c);
        g_basisT[ko*NS + t] = stf((ko & 1) ? -s : c);
        float a = (k == 0) ? (1.0f/NS) : (2.0f/NS);
        float iv = (ko & 1) ? ((k == 0) ? 0.0f : -a*s) : a*c;
        g_ibasis[t*64 + ko]  = stf(iv);
        g_ibasisT[ko*NS + t] = stf(iv);
    }
    if (idx < NM*NC*NC) {
        int k = idx >> 12, r = idx & 4095, o = r >> 6, i = r & 63;
        int src = (i*NC + o)*NM + k;
        g_whA[0][idx] = stf(whr[src]);  g_whA[1][idx] = stf(whi[src]);
        g_wwA[0][idx] = stf(wwr[src]);  g_wwA[1][idx] = stf(wwi[src]);
    }
    if (idx < 8192) {
        g_w1t[idx] = stf(fc1w[idx]);
        g_w2t[idx] = stf(fc2w[idx]);
    }
}

// ---------------- forward DFT over H: Xh[ko][w] = basisT[ko][h] @ x[h][w] ----------------
// smem: sA 64*68 (17408) | sB 64*136 (34816) => 52224
#define FDH_SMEM 52224
__global__ void __launch_bounds__(256) fdftHm(const float* __restrict__ x) {
    extern __shared__ __align__(16) char smem[];
    float* sA = (float*)smem;
    float* sB = (float*)(smem + 17408);
    int slab = blockIdx.x;
    int w0 = blockIdx.y * 128;
    const float* xp = x + (size_t)slab * HW;
    int tid = threadIdx.x, lane = tid & 31, w = tid >> 5;
    int g = lane >> 2, tig = lane & 3;
    int warpM = w & 1, warpN = w >> 1;     // 2 x 4
    float acc[2][4][4] = {};
    for (int hc = 0; hc < NS; hc += 64) {
        for (int idx = tid; idx < 4096; idx += 256) {
            int ko = idx >> 6, hh = idx & 63;
            sA[ko*68 + hh] = g_basisT[ko*NS + hc + hh];
        }
        for (int idx = tid; idx < 8192; idx += 256) {
            int hh = idx >> 7, ww = idx & 127;
            sB[hh*136 + ww] = stf(xp[(size_t)(hc + hh)*NS + w0 + ww]);
        }
        __syncthreads();
        #pragma unroll
        for (int ks = 0; ks < 8; ks++) {
            int k0 = ks * 8;
            u32 af[2][4];
            #pragma unroll
            for (int mt = 0; mt < 2; mt++) {
                int r0 = warpM*32 + mt*16;
                af[mt][0] = __float_as_uint(sA[(r0+g)*68 + k0 + tig]);
                af[mt][1] = __float_as_uint(sA[(r0+g+8)*68 + k0 + tig]);
                af[mt][2] = __float_as_uint(sA[(r0+g)*68 + k0 + tig + 4]);
                af[mt][3] = __float_as_uint(sA[(r0+g+8)*68 + k0 + tig + 4]);
            }
            #pragma unroll
            for (int nt = 0; nt < 4; nt++) {
                int n0 = warpN*32 + nt*8;
                u32 bf[2];
                bf[0] = __float_as_uint(sB[(k0+tig)*136 + n0 + g]);
                bf[1] = __float_as_uint(sB[(k0+tig+4)*136 + n0 + g]);
                mma816(acc[0][nt], af[0], bf);
                mma816(acc[1][nt], af[1], bf);
            }
        }
        __syncthreads();
    }
    float* dst = g_Xh + (size_t)slab * 64 * NS;
    #pragma unroll
    for (int mt = 0; mt < 2; mt++) {
        int row = warpM*32 + mt*16 + g;
        #pragma unroll
        for (int nt = 0; nt < 4; nt++) {
            int col = w0 + warpN*32 + nt*8 + 2*tig;
            *(float2*)&dst[row*NS + col]     = make_float2(acc[mt][nt][0], acc[mt][nt][1]);
            *(float2*)&dst[(row+8)*NS + col] = make_float2(acc[mt][nt][2], acc[mt][nt][3]);
        }
    }
}

// ---------------- forward DFT over W: Xw[ko][h] = basisT[ko][w] @ xT[w][h] ----------------
// smem: sA 64*68 (17408) | sB 64*133 (34048) => 51456
#define FDW_SMEM 51456
__global__ void __launch_bounds__(256) fdftWm(const float* __restrict__ x) {
    extern __shared__ __align__(16) char smem[];
    float* sA = (float*)smem;
    float* sB = (float*)(smem + 17408);
    int slab = blockIdx.x;
    int h0 = blockIdx.y * 128;
    const float* xp = x + (size_t)slab * HW;
    int tid = threadIdx.x, lane = tid & 31, w = tid >> 5;
    int g = lane >> 2, tig = lane & 3;
    int warpM = w & 1, warpN = w >> 1;
    float acc[2][4][4] = {};
    for (int wc = 0; wc < NS; wc += 64) {
        for (int idx = tid; idx < 4096; idx += 256) {
            int ko = idx >> 6, ww = idx & 63;
            sA[ko*68 + ww] = g_basisT[ko*NS + wc + ww];
        }
        for (int idx = tid; idx < 8192; idx += 256) {
            int hh = idx >> 6, ww = idx & 63;
            sB[ww*133 + hh] = stf(xp[(size_t)(h0 + hh)*NS + wc + ww]);
        }
        __syncthreads();
        #pragma unroll
        for (int ks = 0; ks < 8; ks++) {
            int k0 = ks * 8;
            u32 af[2][4];
            #pragma unroll
            for (int mt = 0; mt < 2; mt++) {
                int r0 = warpM*32 + mt*16;
                af[mt][0] = __float_as_uint(sA[(r0+g)*68 + k0 + tig]);
                af[mt][1] = __float_as_uint(sA[(r0+g+8)*68 + k0 + tig]);
                af[mt][2] = __float_as_uint(sA[(r0+g)*68 + k0 + tig + 4]);
                af[mt][3] = __float_as_uint(sA[(r0+g+8)*68 + k0 + tig + 4]);
            }
            #pragma unroll
            for (int nt = 0; nt < 4; nt++) {
                int n0 = warpN*32 + nt*8;
                u32 bf[2];
                bf[0] = __float_as_uint(sB[(k0+tig)*133 + n0 + g]);
                bf[1] = __float_as_uint(sB[(k0+tig+4)*133 + n0 + g]);
                mma816(acc[0][nt], af[0], bf);
                mma816(acc[1][nt], af[1], bf);
            }
        }
        __syncthreads();
    }
    float* dst = g_Xw + (size_t)slab * 64 * NS;
    #pragma unroll
    for (int mt = 0; mt < 2; mt++) {
        int row = warpM*32 + mt*16 + g;
        #pragma unroll
        for (int nt = 0; nt < 4; nt++) {
            int col = h0 + warpN*32 + nt*8 + 2*tig;
            *(float2*)&dst[row*NS + col]     = make_float2(acc[mt][nt][0], acc[mt][nt][1]);
            *(float2*)&dst[(row+8)*NS + col] = make_float2(acc[mt][nt][2], acc[mt][nt][3]);
        }
    }
}

// ---------------- per-mode complex mix: O = W @ X (complex), per (b,k), c0 128-wide ----------------
// smem: sWr 64*68 | sWi 64*68 | sXr 64*136 | sXi 64*136 => 17408*2 + 34816*2 = 104448
#define MIX_SMEM 104448
__global__ void __launch_bounds__(256) mixKm() {
    extern __shared__ __align__(16) char smem[];
    float* sWr = (float*)smem;
    float* sWi = (float*)(smem + 17408);
    float* sXr = (float*)(smem + 34816);
    float* sXi = (float*)(smem + 69632);
    int br = blockIdx.z;
    const float* Xin = br ? g_Xw : g_Xh;
    const float* Wr  = br ? g_wwA[0] : g_whA[0];
    const float* Wi  = br ? g_wwA[1] : g_whA[1];
    float* Out       = br ? g_Ow : g_Oh;
    int b = blockIdx.x >> 5, k = blockIdx.x & 31;
    int c0 = blockIdx.y * 128;
    int tid = threadIdx.x, lane = tid & 31, w = tid >> 5;
    int g = lane >> 2, tig = lane & 3;
    int warpM = w & 1, warpN = w >> 1;
    for (int idx = tid; idx < 4096; idx += 256) {
        int o = idx >> 6, i = idx & 63;
        sWr[o*68 + i] = Wr[k*4096 + o*64 + i];
        sWi[o*68 + i] = Wi[k*4096 + o*64 + i];
    }
    for (int idx = tid; idx < 8192; idx += 256) {
        int i = idx >> 7, c = idx & 127;
        const float* xb = Xin + ((size_t)(b*64 + i)*64 + 2*k)*NS + c0;
        sXr[i*136 + c] = stf(xb[c]);
        sXi[i*136 + c] = stf(xb[NS + c]);
    }
    __syncthreads();
    float accR[2][4][4] = {}, accI[2][4][4] = {};
    #pragma unroll
    for (int ks = 0; ks < 8; ks++) {
        int k0 = ks * 8;
        u32 ar[2][4], ai[2][4], nai[2][4];
        #pragma unroll
        for (int mt = 0; mt < 2; mt++) {
            int r0 = warpM*32 + mt*16;
            ar[mt][0] = __float_as_uint(sWr[(r0+g)*68 + k0 + tig]);
            ar[mt][1] = __float_as_uint(sWr[(r0+g+8)*68 + k0 + tig]);
            ar[mt][2] = __float_as_uint(sWr[(r0+g)*68 + k0 + tig + 4]);
            ar[mt][3] = __float_as_uint(sWr[(r0+g+8)*68 + k0 + tig + 4]);
            ai[mt][0] = __float_as_uint(sWi[(r0+g)*68 + k0 + tig]);
            ai[mt][1] = __float_as_uint(sWi[(r0+g+8)*68 + k0 + tig]);
            ai[mt][2] = __float_as_uint(sWi[(r0+g)*68 + k0 + tig + 4]);
            ai[mt][3] = __float_as_uint(sWi[(r0+g+8)*68 + k0 + tig + 4]);
            #pragma unroll
            for (int j = 0; j < 4; j++) nai[mt][j] = ai[mt][j] ^ 0x80000000u;
        }
        #pragma unroll
        for (int nt = 0; nt < 4; nt++) {
            int n0 = warpN*32 + nt*8;
            u32 bfr[2], bfi[2];
            bfr[0] = __float_as_uint(sXr[(k0+tig)*136 + n0 + g]);
            bfr[1] = __float_as_uint(sXr[(k0+tig+4)*136 + n0 + g]);
            bfi[0] = __float_as_uint(sXi[(k0+tig)*136 + n0 + g]);
            bfi[1] = __float_as_uint(sXi[(k0+tig+4)*136 + n0 + g]);
            #pragma unroll
            for (int mt = 0; mt < 2; mt++) {
                mma816(accR[mt][nt], ar[mt], bfr);
                mma816(accR[mt][nt], nai[mt], bfi);
                mma816(accI[mt][nt], ar[mt], bfi);
                mma816(accI[mt][nt], ai[mt], bfr);
            }
        }
    }
    #pragma unroll
    for (int mt = 0; mt < 2; mt++) {
        #pragma unroll
        for (int nt = 0; nt < 4; nt++) {
            int col = c0 + warpN*32 + nt*8 + 2*tig;
            int o0 = warpM*32 + mt*16 + g;
            float* ob0 = Out + ((size_t)(b*64 + o0)*64 + 2*k)*NS + col;
            *(float2*)ob0        = make_float2(accR[mt][nt][0], accR[mt][nt][1]);
            *(float2*)(ob0 + NS) = make_float2(accI[mt][nt][0], accI[mt][nt][1]);
            float* ob1 = Out + ((size_t)(b*64 + o0 + 8)*64 + 2*k)*NS + col;
            *(float2*)ob1        = make_float2(accR[mt][nt][2], accR[mt][nt][3]);
            *(float2*)(ob1 + NS) = make_float2(accI[mt][nt][2], accI[mt][nt][3]);
        }
    }
}

// ---------------- fused inverse DFTs: f = IBh@Oh + OwT@IBw, 128x64 tiles ----------------
// smem: sAh 128*68 (34816) | sAw 128*69 (35328) | sBh 64*72 (18432) | sBw 64*72 (18432) => 107008
#define INV_SMEM 107008
__global__ void __launch_bounds__(256) invHWm() {
    extern __shared__ __align__(16) char smem[];
    float* sAh = (float*)smem;
    float* sAw = (float*)(smem + 34816);
    float* sBh = (float*)(smem + 70144);
    float* sBw = (float*)(smem + 88576);
    int slab = blockIdx.x;
    int h0 = (blockIdx.y >> 2) * 128, w0 = (blockIdx.y & 3) * 64;
    const float* Oh = g_Oh + (size_t)slab * 64 * NS;
    const float* Ow = g_Ow + (size_t)slab * 64 * NS;
    int tid = threadIdx.x, lane = tid & 31, w = tid >> 5;
    int g = lane >> 2, tig = lane & 3;
    int warpM = w >> 1, warpN = w & 1;     // 4 x 2
    for (int idx = tid; idx < 8192; idx += 256) {
        int r = idx >> 6, c = idx & 63;
        sAh[r*68 + c] = g_ibasis[(h0 + r)*64 + c];
    }
    for (int idx = tid; idx < 8192; idx += 256) {
        int ko = idx >> 7, hh = idx & 127;
        sAw[hh*69 + ko] = stf(Ow[ko*NS + h0 + hh]);
    }
    for (int idx = tid; idx < 4096; idx += 256) {
        int ko = idx >> 6, ww = idx & 63;
        sBh[ko*72 + ww] = stf(Oh[ko*NS + w0 + ww]);
        sBw[ko*72 + ww] = g_ibasisT[ko*NS + w0 + ww];
    }
    __syncthreads();
    float acc[2][4][4] = {};
    #pragma unroll
    for (int ks = 0; ks < 8; ks++) {
        int k0 = ks * 8;
        u32 ah[2][4], aw[2][4];
        #pragma unroll
        for (int mt = 0; mt < 2; mt++) {
            int r0 = warpM*32 + mt*16;
            ah[mt][0] = __float_as_uint(sAh[(r0+g)*68 + k0 + tig]);
            ah[mt][1] = __float_as_uint(sAh[(r0+g+8)*68 + k0 + tig]);
            ah[mt][2] = __float_as_uint(sAh[(r0+g)*68 + k0 + tig + 4]);
            ah[mt][3] = __float_as_uint(sAh[(r0+g+8)*68 + k0 + tig + 4]);
            aw[mt][0] = __float_as_uint(sAw[(r0+g)*69 + k0 + tig]);
            aw[mt][1] = __float_as_uint(sAw[(r0+g+8)*69 + k0 + tig]);
            aw[mt][2] = __float_as_uint(sAw[(r0+g)*69 + k0 + tig + 4]);
            aw[mt][3] = __float_as_uint(sAw[(r0+g+8)*69 + k0 + tig + 4]);
        }
        #pragma unroll
        for (int nt = 0; nt < 4; nt++) {
            int n0 = warpN*32 + nt*8;
            u32 bh[2], bw[2];
            bh[0] = __float_as_uint(sBh[(k0+tig)*72 + n0 + g]);
            bh[1] = __float_as_uint(sBh[(k0+tig+4)*72 + n0 + g]);
            bw[0] = __float_as_uint(sBw[(k0+tig)*72 + n0 + g]);
            bw[1] = __float_as_uint(sBw[(k0+tig+4)*72 + n0 + g]);
            #pragma unroll
            for (int mt = 0; mt < 2; mt++) {
                mma816(acc[mt][nt], ah[mt], bh);
                mma816(acc[mt][nt], aw[mt], bw);
            }
        }
    }
    __syncthreads();   // sAh dead; reuse as output staging [128][68]
    #pragma unroll
    for (int mt = 0; mt < 2; mt++) {
        int r0 = warpM*32 + mt*16 + g;
        #pragma unroll
        for (int nt = 0; nt < 4; nt++) {
            int col = warpN*32 + nt*8 + 2*tig;
            *(float2*)&sAh[r0*68 + col]     = make_float2(acc[mt][nt][0], acc[mt][nt][1]);
            *(float2*)&sAh[(r0+8)*68 + col] = make_float2(acc[mt][nt][2], acc[mt][nt][3]);
        }
    }
    __syncthreads();
    float* fp = g_f + (size_t)slab * HW;
    for (int idx = tid; idx < 8192; idx += 256) {
        int r = idx >> 6, c = idx & 63;
        fp[(size_t)(h0 + r)*NS + w0 + c] = sAh[r*68 + c];
    }
}

// ---------------- mma.sync tf32 FFN: 128 px / block, 512 threads (unchanged) ----------------
#define FFN_SMEM 141312
#define OFF_SA 2048
#define OFF_T1 36864
#define OFF_WB 104448

__global__ void __launch_bounds__(512) ffnM(const float* __restrict__ x,
        const float* __restrict__ b1, const float* __restrict__ lng,
        const float* __restrict__ lnb, const float* __restrict__ b2,
        float* __restrict__ out) {
    extern __shared__ __align__(16) char smem[];
    float* sVec = (float*)smem;
    float* sA = (float*)(smem + OFF_SA);
    float* sT = (float*)(smem + OFF_T1);
    float* sW = (float*)(smem + OFF_WB);
    int tid = threadIdx.x, lane = tid & 31, w = tid >> 5;
    int b  = blockIdx.x >> 9;
    int p0 = (blockIdx.x & 511) * 128;

    if (tid < 128) { sVec[tid] = b1[tid]; sVec[128+tid] = lng[tid]; sVec[256+tid] = lnb[tid]; }
    if (tid < 64) sVec[384+tid] = b2[tid];
    for (int i = tid; i < 2048; i += 512) {
        int c = i >> 5, j4 = (i & 31) * 4;
        *(float4*)&sW[c*136 + j4] = ((const float4*)g_w1t)[i];
    }
    for (int i = tid; i < 8192; i += 512) {
        int c = i >> 7, px = i & 127;
        sA[px*68 + c] = stf(g_f[((size_t)(b*64 + c) << 16) + p0 + px]);
    }
    __syncthreads();

    int warpM = w & 3, warpN = w >> 2;
    int g = lane >> 2, tig = lane & 3;

    float acc[2][4][4] = {};
    #pragma unroll
    for (int ks = 0; ks < 8; ks++) {
        int k0 = ks * 8;
        u32 afr[2][4];
        #pragma unroll
        for (int mt = 0; mt < 2; mt++) {
            const float* ap = sA + (warpM*32 + mt*16)*68 + k0;
            afr[mt][0] = __float_as_uint(ap[g*68 + tig]);
            afr[mt][1] = __float_as_uint(ap[(g+8)*68 + tig]);
            afr[mt][2] = __float_as_uint(ap[g*68 + tig + 4]);
            afr[mt][3] = __float_as_uint(ap[(g+8)*68 + tig + 4]);
        }
        #pragma unroll
        for (int nt = 0; nt < 4; nt++) {
            const float* bp = sW + k0*136 + warpN*32 + nt*8;
            u32 bfr[2];
            bfr[0] = __float_as_uint(bp[tig*136 + g]);
            bfr[1] = __float_as_uint(bp[(tig+4)*136 + g]);
            mma816(acc[0][nt], afr[0], bfr);
            mma816(acc[1][nt], afr[1], bfr);
        }
    }
    #pragma unroll
    for (int mt = 0; mt < 2; mt++) {
        int r0 = warpM*32 + mt*16 + g;
        #pragma unroll
        for (int nt = 0; nt < 4; nt++) {
            int cb = warpN*32 + nt*8 + 2*tig;
            float bb0 = sVec[cb], bb1 = sVec[cb+1];
            sT[r0*132 + cb]     = fmaxf(acc[mt][nt][0] + bb0, 0.f);
            sT[r0*132 + cb + 1] = fmaxf(acc[mt][nt][1] + bb1, 0.f);
            sT[(r0+8)*132 + cb]     = fmaxf(acc[mt][nt][2] + bb0, 0.f);
            sT[(r0+8)*132 + cb + 1] = fmaxf(acc[mt][nt][3] + bb1, 0.f);
        }
    }
    __syncthreads();

    for (int p8 = 0; p8 < 8; p8++) {
        int px = w*8 + p8;
        float4 v = *(float4*)&sT[px*132 + lane*4];
        float s1 = v.x + v.y + v.z + v.w;
        float s2 = v.x*v.x + v.y*v.y + v.z*v.z + v.w*v.w;
        #pragma unroll
        for (int o = 16; o > 0; o >>= 1) {
            s1 += __shfl_xor_sync(0xFFFFFFFFu, s1, o);
            s2 += __shfl_xor_sync(0xFFFFFFFFu, s2, o);
        }
        float mu  = s1 * (1.0f/128.0f);
        float var = s2 * (1.0f/128.0f) - mu*mu;
        float inv = rsqrtf(var + 1e-5f);
        float4 gm = *(float4*)&sVec[128 + lane*4];
        float4 bt = *(float4*)&sVec[256 + lane*4];
        uint4 q;
        q.x = tf32b((v.x - mu)*inv*gm.x + bt.x);
        q.y = tf32b((v.y - mu)*inv*gm.y + bt.y);
        q.z = tf32b((v.z - mu)*inv*gm.z + bt.z);
        q.w = tf32b((v.w - mu)*inv*gm.w + bt.w);
        *(uint4*)&sT[px*132 + lane*4] = q;
    }
    __syncthreads();

    for (int i = tid; i < 2048; i += 512) {
        int j = i >> 4, o4 = (i & 15) * 4;
        *(float4*)&sW[j*72 + o4] = ((const float4*)g_w2t)[i];
    }
    __syncthreads();

    float acc2[2][2][4] = {};
    #pragma unroll
    for (int ks = 0; ks < 16; ks++) {
        int k0 = ks * 8;
        u32 afr[2][4];
        #pragma unroll
        for (int mt = 0; mt < 2; mt++) {
            const float* ap = sT + (warpM*32 + mt*16)*132 + k0;
            afr[mt][0] = __float_as_uint(ap[g*132 + tig]);
            afr[mt][1] = __float_as_uint(ap[(g+8)*132 + tig]);
            afr[mt][2] = __float_as_uint(ap[g*132 + tig + 4]);
            afr[mt][3] = __float_as_uint(ap[(g+8)*132 + tig + 4]);
        }
        #pragma unroll
        for (int nt = 0; nt < 2; nt++) {
            const float* bp = sW + k0*72 + warpN*16 + nt*8;
            u32 bfr[2];
            bfr[0] = __float_as_uint(bp[tig*72 + g]);
            bfr[1] = __float_as_uint(bp[(tig+4)*72 + g]);
            mma816(acc2[0][nt], afr[0], bfr);
            mma816(acc2[1][nt], afr[1], bfr);
        }
    }
    __syncthreads();
    float* sO = sA;
    #pragma unroll
    for (int mt = 0; mt < 2; mt++) {
        int r0 = warpM*32 + mt*16 + g;
        #pragma unroll
        for (int nt = 0; nt < 2; nt++) {
            int ob = warpN*16 + nt*8 + 2*tig;
            float bb0 = sVec[384 + ob], bb1 = sVec[384 + ob + 1];
            sO[ob*132 + r0]       = acc2[mt][nt][0] + bb0;
            sO[(ob+1)*132 + r0]   = acc2[mt][nt][1] + bb1;
            sO[ob*132 + r0 + 8]   = acc2[mt][nt][2] + bb0;
            sO[(ob+1)*132 + r0+8] = acc2[mt][nt][3] + bb1;
        }
    }
    __syncthreads();
    for (int i = tid; i < 8192; i += 512) {
        int o = i >> 7, px = i & 127;
        size_t gg = ((size_t)(b*64 + o) << 16) + p0 + px;
        out[gg] = sO[o*132 + px] + x[gg];
    }
}

// ---------------- launch ----------------
extern "C" void kernel_launch(void* const* d_in, const int* in_sizes, int n_in,
                              void* d_out, int out_size) {
    const float* x    = (const float*)d_in[0];
    const float* whr  = (const float*)d_in[1];
    const float* whi  = (const float*)d_in[2];
    const float* wwr  = (const float*)d_in[3];
    const float* wwi  = (const float*)d_in[4];
    const float* fc1w = (const float*)d_in[5];
    const float* fc1b = (const float*)d_in[6];
    const float* lng  = (const float*)d_in[7];
    const float* lnb  = (const float*)d_in[8];
    const float* fc2w = (const float*)d_in[9];
    const float* fc2b = (const float*)d_in[10];
    float* out = (float*)d_out;

    cudaFuncSetAttribute(fdftHm, cudaFuncAttributeMaxDynamicSharedMemorySize, FDH_SMEM);
    cudaFuncSetAttribute(fdftWm, cudaFuncAttributeMaxDynamicSharedMemorySize, FDW_SMEM);
    cudaFuncSetAttribute(mixKm,  cudaFuncAttributeMaxDynamicSharedMemorySize, MIX_SMEM);
    cudaFuncSetAttribute(invHWm, cudaFuncAttributeMaxDynamicSharedMemorySize, INV_SMEM);
    cudaFuncSetAttribute(ffnM,   cudaFuncAttributeMaxDynamicSharedMemorySize, FFN_SMEM);

    initK<<<512, 256>>>(whr, whi, wwr, wwi, fc1w, fc2w);
    fdftHm<<<dim3(512, 2), 256, FDH_SMEM>>>(x);
    fdftWm<<<dim3(512, 2), 256, FDW_SMEM>>>(x);
    mixKm<<<dim3(256, 2, 2), 256, MIX_SMEM>>>();
    invHWm<<<dim3(512, 8), 256, INV_SMEM>>>();
    ffnM<<<4096, 512, FFN_SMEM>>>(x, fc1b, lng, lnb, fc2b, out);
}

// round 16
// speedup vs baseline: 1.5174x; 1.3257x over previous
#include <cuda_runtime.h>
#include <math.h>

#define NB 8
#define NC 64
#define NS 256
#define NM 32
#define HW (NS*NS)

typedef unsigned long long u64;
typedef unsigned int u32;

__device__ __forceinline__ u32 tf32b(float f) {
    u32 u; asm("cvt.rna.tf32.f32 %0, %1;" : "=r"(u) : "f"(f)); return u;
}
__device__ __forceinline__ float stf(float f) { return __uint_as_float(tf32b(f)); }
__device__ __forceinline__ void mma816(float* d, const u32* a, const u32* b) {
    asm volatile("mma.sync.aligned.m16n8k8.row.col.f32.tf32.tf32.f32 "
        "{%0,%1,%2,%3}, {%4,%5,%6,%7}, {%8,%9}, {%0,%1,%2,%3};"
        : "+f"(d[0]), "+f"(d[1]), "+f"(d[2]), "+f"(d[3])
        : "r"(a[0]), "r"(a[1]), "r"(a[2]), "r"(a[3]), "r"(b[0]), "r"(b[1]));
}

// ---------------- static device scratch ----------------
__device__ float g_basisT[64*NS];      // fwd DFT [ko][t] tf32-rounded
__device__ float g_ibasis[NS*64];      // inv DFT [t][ko] tf32-rounded
__device__ float g_ibasisT[64*NS];     // inv DFT [ko][t] tf32-rounded
__device__ float g_whA[2][NM*NC*NC];   // [re/im][k][o][i] tf32-rounded
__device__ float g_wwA[2][NM*NC*NC];
__device__ float g_w1t[8192];          // fc1w tf32 [c][j]
__device__ float g_w2t[8192];          // fc2w tf32 [j][o]
__device__ float g_Xh[(size_t)NB*NC*64*NS];
__device__ float g_Xw[(size_t)NB*NC*64*NS];
__device__ float g_Oh[(size_t)NB*NC*64*NS];
__device__ float g_Ow[(size_t)NB*NC*64*NS];
__device__ float g_f [(size_t)NB*NC*HW];

// ---------------- init ----------------
__global__ void initK(const float* __restrict__ whr, const float* __restrict__ whi,
                      const float* __restrict__ wwr, const float* __restrict__ wwi,
                      const float* __restrict__ fc1w, const float* __restrict__ fc2w) {
    int idx = blockIdx.x * 256 + threadIdx.x;      // covers 131072
    if (idx < NS*64) {
        int t = idx >> 6, ko = idx & 63, k = ko >> 1;
        float s, c;
        sincospif((float)((k * t) & 255) / 128.0f, &s, &c);
        g_basisT[ko*NS + t] = stf((ko & 1) ? -s : c);
        float a = (k == 0) ? (1.0f/NS) : (2.0f/NS);
        float iv = (ko & 1) ? ((k == 0) ? 0.0f : -a*s) : a*c;
        g_ibasis[t*64 + ko]  = stf(iv);
        g_ibasisT[ko*NS + t] = stf(iv);
    }
    if (idx < NM*NC*NC) {
        int k = idx >> 12, r = idx & 4095, o = r >> 6, i = r & 63;
        int src = (i*NC + o)*NM + k;
        g_whA[0][idx] = stf(whr[src]);  g_whA[1][idx] = stf(whi[src]);
        g_wwA[0][idx] = stf(wwr[src]);  g_wwA[1][idx] = stf(wwi[src]);
    }
    if (idx < 8192) {
        g_w1t[idx] = stf(fc1w[idx]);
        g_w2t[idx] = stf(fc2w[idx]);
    }
}

// ---------------- forward DFT over H: Xh[ko][w] = basisT[ko][h] @ x[h][w] ----------------
// smem: sA 64*68 (17408) | sB 64*136 (34816) => 52224
#define FDH_SMEM 52224
__global__ void __launch_bounds__(256) fdftHm(const float* __restrict__ x) {
    extern __shared__ __align__(16) char smem[];
    float* sA = (float*)smem;
    float* sB = (float*)(smem + 17408);
    int slab = blockIdx.x;
    int w0 = blockIdx.y * 128;
    const float* xp = x + (size_t)slab * HW;
    int tid = threadIdx.x, lane = tid & 31, w = tid >> 5;
    int g = lane >> 2, tig = lane & 3;
    int warpM = w & 1, warpN = w >> 1;     // 2 x 4
    float acc[2][4][4] = {};
    for (int hc = 0; hc < NS; hc += 64) {
        for (int idx = tid; idx < 4096; idx += 256) {
            int ko = idx >> 6, hh = idx & 63;
            sA[ko*68 + hh] = g_basisT[ko*NS + hc + hh];
        }
        for (int idx = tid; idx < 8192; idx += 256) {
            int hh = idx >> 7, ww = idx & 127;
            sB[hh*136 + ww] = stf(xp[(size_t)(hc + hh)*NS + w0 + ww]);
        }
        __syncthreads();
        #pragma unroll
        for (int ks = 0; ks < 8; ks++) {
            int k0 = ks * 8;
            u32 af[2][4];
            #pragma unroll
            for (int mt = 0; mt < 2; mt++) {
                int r0 = warpM*32 + mt*16;
                af[mt][0] = __float_as_uint(sA[(r0+g)*68 + k0 + tig]);
                af[mt][1] = __float_as_uint(sA[(r0+g+8)*68 + k0 + tig]);
                af[mt][2] = __float_as_uint(sA[(r0+g)*68 + k0 + tig + 4]);
                af[mt][3] = __float_as_uint(sA[(r0+g+8)*68 + k0 + tig + 4]);
            }
            #pragma unroll
            for (int nt = 0; nt < 4; nt++) {
                int n0 = warpN*32 + nt*8;
                u32 bf[2];
                bf[0] = __float_as_uint(sB[(k0+tig)*136 + n0 + g]);
                bf[1] = __float_as_uint(sB[(k0+tig+4)*136 + n0 + g]);
                mma816(acc[0][nt], af[0], bf);
                mma816(acc[1][nt], af[1], bf);
            }
        }
        __syncthreads();
    }
    float* dst = g_Xh + (size_t)slab * 64 * NS;
    #pragma unroll
    for (int mt = 0; mt < 2; mt++) {
        int row = warpM*32 + mt*16 + g;
        #pragma unroll
        for (int nt = 0; nt < 4; nt++) {
            int col = w0 + warpN*32 + nt*8 + 2*tig;
            *(float2*)&dst[row*NS + col]     = make_float2(acc[mt][nt][0], acc[mt][nt][1]);
            *(float2*)&dst[(row+8)*NS + col] = make_float2(acc[mt][nt][2], acc[mt][nt][3]);
        }
    }
}

// ---------------- forward DFT over W: Xw[ko][h] = basisT[ko][w] @ xT[w][h] ----------------
// smem: sA 64*68 (17408) | sB 64*133 (34048) => 51456
#define FDW_SMEM 51456
__global__ void __launch_bounds__(256) fdftWm(const float* __restrict__ x) {
    extern __shared__ __align__(16) char smem[];
    float* sA = (float*)smem;
    float* sB = (float*)(smem + 17408);
    int slab = blockIdx.x;
    int h0 = blockIdx.y * 128;
    const float* xp = x + (size_t)slab * HW;
    int tid = threadIdx.x, lane = tid & 31, w = tid >> 5;
    int g = lane >> 2, tig = lane & 3;
    int warpM = w & 1, warpN = w >> 1;
    float acc[2][4][4] = {};
    for (int wc = 0; wc < NS; wc += 64) {
        for (int idx = tid; idx < 4096; idx += 256) {
            int ko = idx >> 6, ww = idx & 63;
            sA[ko*68 + ww] = g_basisT[ko*NS + wc + ww];
        }
        for (int idx = tid; idx < 8192; idx += 256) {
            int hh = idx >> 6, ww = idx & 63;
            sB[ww*133 + hh] = stf(xp[(size_t)(h0 + hh)*NS + wc + ww]);
        }
        __syncthreads();
        #pragma unroll
        for (int ks = 0; ks < 8; ks++) {
            int k0 = ks * 8;
            u32 af[2][4];
            #pragma unroll
            for (int mt = 0; mt < 2; mt++) {
                int r0 = warpM*32 + mt*16;
                af[mt][0] = __float_as_uint(sA[(r0+g)*68 + k0 + tig]);
                af[mt][1] = __float_as_uint(sA[(r0+g+8)*68 + k0 + tig]);
                af[mt][2] = __float_as_uint(sA[(r0+g)*68 + k0 + tig + 4]);
                af[mt][3] = __float_as_uint(sA[(r0+g+8)*68 + k0 + tig + 4]);
            }
            #pragma unroll
            for (int nt = 0; nt < 4; nt++) {
                int n0 = warpN*32 + nt*8;
                u32 bf[2];
                bf[0] = __float_as_uint(sB[(k0+tig)*133 + n0 + g]);
                bf[1] = __float_as_uint(sB[(k0+tig+4)*133 + n0 + g]);
                mma816(acc[0][nt], af[0], bf);
                mma816(acc[1][nt], af[1], bf);
            }
        }
        __syncthreads();
    }
    float* dst = g_Xw + (size_t)slab * 64 * NS;
    #pragma unroll
    for (int mt = 0; mt < 2; mt++) {
        int row = warpM*32 + mt*16 + g;
        #pragma unroll
        for (int nt = 0; nt < 4; nt++) {
            int col = h0 + warpN*32 + nt*8 + 2*tig;
            *(float2*)&dst[row*NS + col]     = make_float2(acc[mt][nt][0], acc[mt][nt][1]);
            *(float2*)&dst[(row+8)*NS + col] = make_float2(acc[mt][nt][2], acc[mt][nt][3]);
        }
    }
}

// ---------------- per-mode complex mix: O = W @ X (complex), per (b,k), c0 128-wide ----------------
// smem: sWr 64*68 | sWi 64*68 | sXr 64*136 | sXi 64*136 => 104448
#define MIX_SMEM 104448
__global__ void __launch_bounds__(256) mixKm() {
    extern __shared__ __align__(16) char smem[];
    float* sWr = (float*)smem;
    float* sWi = (float*)(smem + 17408);
    float* sXr = (float*)(smem + 34816);
    float* sXi = (float*)(smem + 69632);
    int br = blockIdx.z;
    const float* Xin = br ? g_Xw : g_Xh;
    const float* Wr  = br ? g_wwA[0] : g_whA[0];
    const float* Wi  = br ? g_wwA[1] : g_whA[1];
    float* Out       = br ? g_Ow : g_Oh;
    int b = blockIdx.x >> 5, k = blockIdx.x & 31;
    int c0 = blockIdx.y * 128;
    int tid = threadIdx.x, lane = tid & 31, w = tid >> 5;
    int g = lane >> 2, tig = lane & 3;
    int warpM = w & 1, warpN = w >> 1;
    for (int idx = tid; idx < 4096; idx += 256) {
        int o = idx >> 6, i = idx & 63;
        sWr[o*68 + i] = Wr[k*4096 + o*64 + i];
        sWi[o*68 + i] = Wi[k*4096 + o*64 + i];
    }
    for (int idx = tid; idx < 8192; idx += 256) {
        int i = idx >> 7, c = idx & 127;
        const float* xb = Xin + ((size_t)(b*64 + i)*64 + 2*k)*NS + c0;
        sXr[i*136 + c] = stf(xb[c]);
        sXi[i*136 + c] = stf(xb[NS + c]);
    }
    __syncthreads();
    float accR[2][4][4] = {}, accI[2][4][4] = {};
    #pragma unroll
    for (int ks = 0; ks < 8; ks++) {
        int k0 = ks * 8;
        u32 ar[2][4], ai[2][4], nai[2][4];
        #pragma unroll
        for (int mt = 0; mt < 2; mt++) {
            int r0 = warpM*32 + mt*16;
            ar[mt][0] = __float_as_uint(sWr[(r0+g)*68 + k0 + tig]);
            ar[mt][1] = __float_as_uint(sWr[(r0+g+8)*68 + k0 + tig]);
            ar[mt][2] = __float_as_uint(sWr[(r0+g)*68 + k0 + tig + 4]);
            ar[mt][3] = __float_as_uint(sWr[(r0+g+8)*68 + k0 + tig + 4]);
            ai[mt][0] = __float_as_uint(sWi[(r0+g)*68 + k0 + tig]);
            ai[mt][1] = __float_as_uint(sWi[(r0+g+8)*68 + k0 + tig]);
            ai[mt][2] = __float_as_uint(sWi[(r0+g)*68 + k0 + tig + 4]);
            ai[mt][3] = __float_as_uint(sWi[(r0+g+8)*68 + k0 + tig + 4]);
            #pragma unroll
            for (int j = 0; j < 4; j++) nai[mt][j] = ai[mt][j] ^ 0x80000000u;
        }
        #pragma unroll
        for (int nt = 0; nt < 4; nt++) {
            int n0 = warpN*32 + nt*8;
            u32 bfr[2], bfi[2];
            bfr[0] = __float_as_uint(sXr[(k0+tig)*136 + n0 + g]);
            bfr[1] = __float_as_uint(sXr[(k0+tig+4)*136 + n0 + g]);
            bfi[0] = __float_as_uint(sXi[(k0+tig)*136 + n0 + g]);
            bfi[1] = __float_as_uint(sXi[(k0+tig+4)*136 + n0 + g]);
            #pragma unroll
            for (int mt = 0; mt < 2; mt++) {
                mma816(accR[mt][nt], ar[mt], bfr);
                mma816(accR[mt][nt], nai[mt], bfi);
                mma816(accI[mt][nt], ar[mt], bfi);
                mma816(accI[mt][nt], ai[mt], bfr);
            }
        }
    }
    #pragma unroll
    for (int mt = 0; mt < 2; mt++) {
        #pragma unroll
        for (int nt = 0; nt < 4; nt++) {
            int col = c0 + warpN*32 + nt*8 + 2*tig;
            int o0 = warpM*32 + mt*16 + g;
            float* ob0 = Out + ((size_t)(b*64 + o0)*64 + 2*k)*NS + col;
            *(float2*)ob0        = make_float2(accR[mt][nt][0], accR[mt][nt][1]);
            *(float2*)(ob0 + NS) = make_float2(accI[mt][nt][0], accI[mt][nt][1]);
            float* ob1 = Out + ((size_t)(b*64 + o0 + 8)*64 + 2*k)*NS + col;
            *(float2*)ob1        = make_float2(accR[mt][nt][2], accR[mt][nt][3]);
            *(float2*)(ob1 + NS) = make_float2(accI[mt][nt][2], accI[mt][nt][3]);
        }
    }
}

// ---------------- fused inverse DFTs: f = IBh@Oh + OwT@IBw, 128x64 tiles ----------------
// smem: sAh 128*68 (34816) | sAw 128*69 (35328) | sBh 64*72 (18432) | sBw 64*72 (18432) => 107008
#define INV_SMEM 107008
__global__ void __launch_bounds__(256) invHWm() {
    extern __shared__ __align__(16) char smem[];
    float* sAh = (float*)smem;
    float* sAw = (float*)(smem + 34816);
    float* sBh = (float*)(smem + 70144);
    float* sBw = (float*)(smem + 88576);
    int slab = blockIdx.x;
    int h0 = (blockIdx.y >> 2) * 128, w0 = (blockIdx.y & 3) * 64;
    const float* Oh = g_Oh + (size_t)slab * 64 * NS;
    const float* Ow = g_Ow + (size_t)slab * 64 * NS;
    int tid = threadIdx.x, lane = tid & 31, w = tid >> 5;
    int g = lane >> 2, tig = lane & 3;
    int warpM = w >> 1, warpN = w & 1;     // 4 x 2
    for (int idx = tid; idx < 8192; idx += 256) {
        int r = idx >> 6, c = idx & 63;
        sAh[r*68 + c] = g_ibasis[(h0 + r)*64 + c];
    }
    for (int idx = tid; idx < 8192; idx += 256) {
        int ko = idx >> 7, hh = idx & 127;
        sAw[hh*69 + ko] = stf(Ow[ko*NS + h0 + hh]);
    }
    for (int idx = tid; idx < 4096; idx += 256) {
        int ko = idx >> 6, ww = idx & 63;
        sBh[ko*72 + ww] = stf(Oh[ko*NS + w0 + ww]);
        sBw[ko*72 + ww] = g_ibasisT[ko*NS + w0 + ww];
    }
    __syncthreads();
    float acc[2][4][4] = {};
    #pragma unroll
    for (int ks = 0; ks < 8; ks++) {
        int k0 = ks * 8;
        u32 ah[2][4], aw[2][4];
        #pragma unroll
        for (int mt = 0; mt < 2; mt++) {
            int r0 = warpM*32 + mt*16;
            ah[mt][0] = __float_as_uint(sAh[(r0+g)*68 + k0 + tig]);
            ah[mt][1] = __float_as_uint(sAh[(r0+g+8)*68 + k0 + tig]);
            ah[mt][2] = __float_as_uint(sAh[(r0+g)*68 + k0 + tig + 4]);
            ah[mt][3] = __float_as_uint(sAh[(r0+g+8)*68 + k0 + tig + 4]);
            aw[mt][0] = __float_as_uint(sAw[(r0+g)*69 + k0 + tig]);
            aw[mt][1] = __float_as_uint(sAw[(r0+g+8)*69 + k0 + tig]);
            aw[mt][2] = __float_as_uint(sAw[(r0+g)*69 + k0 + tig + 4]);
            aw[mt][3] = __float_as_uint(sAw[(r0+g+8)*69 + k0 + tig + 4]);
        }
        #pragma unroll
        for (int nt = 0; nt < 4; nt++) {
            int n0 = warpN*32 + nt*8;
            u32 bh[2], bw[2];
            bh[0] = __float_as_uint(sBh[(k0+tig)*72 + n0 + g]);
            bh[1] = __float_as_uint(sBh[(k0+tig+4)*72 + n0 + g]);
            bw[0] = __float_as_uint(sBw[(k0+tig)*72 + n0 + g]);
            bw[1] = __float_as_uint(sBw[(k0+tig+4)*72 + n0 + g]);
            #pragma unroll
            for (int mt = 0; mt < 2; mt++) {
                mma816(acc[mt][nt], ah[mt], bh);
                mma816(acc[mt][nt], aw[mt], bw);
            }
        }
    }
    __syncthreads();   // sAh dead; reuse as output staging [128][68]
    #pragma unroll
    for (int mt = 0; mt < 2; mt++) {
        int r0 = warpM*32 + mt*16 + g;
        #pragma unroll
        for (int nt = 0; nt < 4; nt++) {
            int col = warpN*32 + nt*8 + 2*tig;
            *(float2*)&sAh[r0*68 + col]     = make_float2(acc[mt][nt][0], acc[mt][nt][1]);
            *(float2*)&sAh[(r0+8)*68 + col] = make_float2(acc[mt][nt][2], acc[mt][nt][3]);
        }
    }
    __syncthreads();
    float* fp = g_f + (size_t)slab * HW;
    for (int idx = tid; idx < 8192; idx += 256) {
        int r = idx >> 6, c = idx & 63;
        fp[(size_t)(h0 + r)*NS + w0 + c] = sAh[r*68 + c];
    }
}

// ---------------- mma.sync tf32 FFN: 128 px / block, 512 threads, aliased smem -> 2 CTAs/SM ----------------
// smem: sVec 2048 | sT 128*132 f32 (67584) [sA aliases its first 34816 B] | sW 36864 [sO aliases] => 106496
#define FFN_SMEM 106496
#define OFF_T1 2048
#define OFF_WB 69632

__global__ void __launch_bounds__(512) ffnM(const float* __restrict__ x,
        const float* __restrict__ b1, const float* __restrict__ lng,
        const float* __restrict__ lnb, const float* __restrict__ b2,
        float* __restrict__ out) {
    extern __shared__ __align__(16) char smem[];
    float* sVec = (float*)smem;
    float* sT = (float*)(smem + OFF_T1);
    float* sA = sT;                        // aliased: A tile dead after GEMM1 (sync guards)
    float* sW = (float*)(smem + OFF_WB);
    int tid = threadIdx.x, lane = tid & 31, w = tid >> 5;
    int b  = blockIdx.x >> 9;
    int p0 = (blockIdx.x & 511) * 128;

    if (tid < 128) { sVec[tid] = b1[tid]; sVec[128+tid] = lng[tid]; sVec[256+tid] = lnb[tid]; }
    if (tid < 64) sVec[384+tid] = b2[tid];
    for (int i = tid; i < 2048; i += 512) {
        int c = i >> 5, j4 = (i & 31) * 4;
        *(float4*)&sW[c*136 + j4] = ((const float4*)g_w1t)[i];
    }
    for (int i = tid; i < 8192; i += 512) {
        int c = i >> 7, px = i & 127;
        sA[px*68 + c] = stf(g_f[((size_t)(b*64 + c) << 16) + p0 + px]);
    }
    __syncthreads();

    int warpM = w & 3, warpN = w >> 2;
    int g = lane >> 2, tig = lane & 3;

    float acc[2][4][4] = {};
    #pragma unroll
    for (int ks = 0; ks < 8; ks++) {
        int k0 = ks * 8;
        u32 afr[2][4];
        #pragma unroll
        for (int mt = 0; mt < 2; mt++) {
            const float* ap = sA + (warpM*32 + mt*16)*68 + k0;
            afr[mt][0] = __float_as_uint(ap[g*68 + tig]);
            afr[mt][1] = __float_as_uint(ap[(g+8)*68 + tig]);
            afr[mt][2] = __float_as_uint(ap[g*68 + tig + 4]);
            afr[mt][3] = __float_as_uint(ap[(g+8)*68 + tig + 4]);
        }
        #pragma unroll
        for (int nt = 0; nt < 4; nt++) {
            const float* bp = sW + k0*136 + warpN*32 + nt*8;
            u32 bfr[2];
            bfr[0] = __float_as_uint(bp[tig*136 + g]);
            bfr[1] = __float_as_uint(bp[(tig+4)*136 + g]);
            mma816(acc[0][nt], afr[0], bfr);
            mma816(acc[1][nt], afr[1], bfr);
        }
    }
    __syncthreads();   // all warps done reading sA before epilogue overwrites its region (sT alias)
    #pragma unroll
    for (int mt = 0; mt < 2; mt++) {
        int r0 = warpM*32 + mt*16 + g;
        #pragma unroll
        for (int nt = 0; nt < 4; nt++) {
            int cb = warpN*32 + nt*8 + 2*tig;
            float bb0 = sVec[cb], bb1 = sVec[cb+1];
            sT[r0*132 + cb]     = fmaxf(acc[mt][nt][0] + bb0, 0.f);
            sT[r0*132 + cb + 1] = fmaxf(acc[mt][nt][1] + bb1, 0.f);
            sT[(r0+8)*132 + cb]     = fmaxf(acc[mt][nt][2] + bb0, 0.f);
            sT[(r0+8)*132 + cb + 1] = fmaxf(acc[mt][nt][3] + bb1, 0.f);
        }
    }
    __syncthreads();

    for (int p8 = 0; p8 < 8; p8++) {
        int px = w*8 + p8;
        float4 v = *(float4*)&sT[px*132 + lane*4];
        float s1 = v.x + v.y + v.z + v.w;
        float s2 = v.x*v.x + v.y*v.y + v.z*v.z + v.w*v.w;
        #pragma unroll
        for (int o = 16; o > 0; o >>= 1) {
            s1 += __shfl_xor_sync(0xFFFFFFFFu, s1, o);
            s2 += __shfl_xor_sync(0xFFFFFFFFu, s2, o);
        }
        float mu  = s1 * (1.0f/128.0f);
        float var = s2 * (1.0f/128.0f) - mu*mu;
        float inv = rsqrtf(var + 1e-5f);
        float4 gm = *(float4*)&sVec[128 + lane*4];
        float4 bt = *(float4*)&sVec[256 + lane*4];
        uint4 q;
        q.x = tf32b((v.x - mu)*inv*gm.x + bt.x);
        q.y = tf32b((v.y - mu)*inv*gm.y + bt.y);
        q.z = tf32b((v.z - mu)*inv*gm.z + bt.z);
        q.w = tf32b((v.w - mu)*inv*gm.w + bt.w);
        *(uint4*)&sT[px*132 + lane*4] = q;
    }
    __syncthreads();

    for (int i = tid; i < 2048; i += 512) {
        int j = i >> 4, o4 = (i & 15) * 4;
        *(float4*)&sW[j*72 + o4] = ((const float4*)g_w2t)[i];
    }
    __syncthreads();

    float acc2[2][2][4] = {};
    #pragma unroll
    for (int ks = 0; ks < 16; ks++) {
        int k0 = ks * 8;
        u32 afr[2][4];
        #pragma unroll
        for (int mt = 0; mt < 2; mt++) {
            const float* ap = sT + (warpM*32 + mt*16)*132 + k0;
            afr[mt][0] = __float_as_uint(ap[g*132 + tig]);
            afr[mt][1] = __float_as_uint(ap[(g+8)*132 + tig]);
            afr[mt][2] = __float_as_uint(ap[g*132 + tig + 4]);
            afr[mt][3] = __float_as_uint(ap[(g+8)*132 + tig + 4]);
        }
        #pragma unroll
        for (int nt = 0; nt < 2; nt++) {
            const float* bp = sW + k0*72 + warpN*16 + nt*8;
            u32 bfr[2];
            bfr[0] = __float_as_uint(bp[tig*72 + g]);
            bfr[1] = __float_as_uint(bp[(tig+4)*72 + g]);
            mma816(acc2[0][nt], afr[0], bfr);
            mma816(acc2[1][nt], afr[1], bfr);
        }
    }
    __syncthreads();   // all warps done reading sW before sO overwrites it
    float* sO = sW;    // aliased: weight tile dead after GEMM2; sO is 64*132*4 = 33792 <= 36864
    #pragma unroll
    for (int mt = 0; mt < 2; mt++) {
        int r0 = warpM*32 + mt*16 + g;
        #pragma unroll
        for (int nt = 0; nt < 2; nt++) {
            int ob = warpN*16 + nt*8 + 2*tig;
            float bb0 = sVec[384 + ob], bb1 = sVec[384 + ob + 1];
            sO[ob*132 + r0]       = acc2[mt][nt][0] + bb0;
            sO[(ob+1)*132 + r0]   = acc2[mt][nt][1] + bb1;
            sO[ob*132 + r0 + 8]   = acc2[mt][nt][2] + bb0;
            sO[(ob+1)*132 + r0+8] = acc2[mt][nt][3] + bb1;
        }
    }
    __syncthreads();
    for (int i = tid; i < 8192; i += 512) {
        int o = i >> 7, px = i & 127;
        size_t gg = ((size_t)(b*64 + o) << 16) + p0 + px;
        out[gg] = sO[o*132 + px] + x[gg];
    }
}

// ---------------- launch ----------------
extern "C" void kernel_launch(void* const* d_in, const int* in_sizes, int n_in,
                              void* d_out, int out_size) {
    const float* x    = (const float*)d_in[0];
    const float* whr  = (const float*)d_in[1];
    const float* whi  = (const float*)d_in[2];
    const float* wwr  = (const float*)d_in[3];
    const float* wwi  = (const float*)d_in[4];
    const float* fc1w = (const float*)d_in[5];
    const float* fc1b = (const float*)d_in[6];
    const float* lng  = (const float*)d_in[7];
    const float* lnb  = (const float*)d_in[8];
    const float* fc2w = (const float*)d_in[9];
    const float* fc2b = (const float*)d_in[10];
    float* out = (float*)d_out;

    cudaFuncSetAttribute(fdftHm, cudaFuncAttributeMaxDynamicSharedMemorySize, FDH_SMEM);
    cudaFuncSetAttribute(fdftWm, cudaFuncAttributeMaxDynamicSharedMemorySize, FDW_SMEM);
    cudaFuncSetAttribute(mixKm,  cudaFuncAttributeMaxDynamicSharedMemorySize, MIX_SMEM);
    cudaFuncSetAttribute(invHWm, cudaFuncAttributeMaxDynamicSharedMemorySize, INV_SMEM);
    cudaFuncSetAttribute(ffnM,   cudaFuncAttributeMaxDynamicSharedMemorySize, FFN_SMEM);

    initK<<<512, 256>>>(whr, whi, wwr, wwi, fc1w, fc2w);
    fdftHm<<<dim3(512, 2), 256, FDH_SMEM>>>(x);
    fdftWm<<<dim3(512, 2), 256, FDW_SMEM>>>(x);
    mixKm<<<dim3(256, 2, 2), 256, MIX_SMEM>>>();
    invHWm<<<dim3(512, 8), 256, INV_SMEM>>>();
    ffnM<<<4096, 512, FFN_SMEM>>>(x, fc1b, lng, lnb, fc2b, out);
}

// round 17
// speedup vs baseline: 1.9719x; 1.2996x over previous
#include <cuda_runtime.h>
#include <math.h>

#define NB 8
#define NC 64
#define NS 256
#define NM 32
#define HW (NS*NS)

typedef unsigned long long u64;
typedef unsigned int u32;

__device__ __forceinline__ u32 tf32b(float f) {
    u32 u; asm("cvt.rna.tf32.f32 %0, %1;" : "=r"(u) : "f"(f)); return u;
}
__device__ __forceinline__ float stf(float f) { return __uint_as_float(tf32b(f)); }
__device__ __forceinline__ void mma816(float* d, const u32* a, const u32* b) {
    asm volatile("mma.sync.aligned.m16n8k8.row.col.f32.tf32.tf32.f32 "
        "{%0,%1,%2,%3}, {%4,%5,%6,%7}, {%8,%9}, {%0,%1,%2,%3};"
        : "+f"(d[0]), "+f"(d[1]), "+f"(d[2]), "+f"(d[3])
        : "r"(a[0]), "r"(a[1]), "r"(a[2]), "r"(a[3]), "r"(b[0]), "r"(b[1]));
}
__device__ __forceinline__ u32 s2u(const void* p) {
    u32 a; asm("{ .reg .u64 t; cvta.to.shared.u64 t, %1; cvt.u32.u64 %0, t; }" : "=r"(a) : "l"(p));
    return a;
}
#define CP16(d, s) asm volatile("cp.async.ca.shared.global [%0], [%1], 16;" :: "r"(d), "l"(s))
#define CP4(d, s)  asm volatile("cp.async.ca.shared.global [%0], [%1], 4;"  :: "r"(d), "l"(s))
#define CPWAIT()   asm volatile("cp.async.commit_group;\ncp.async.wait_group 0;" ::: "memory")

// ---------------- static device scratch ----------------
__device__ float g_basisT[64*NS];      // fwd DFT [ko][t] tf32-rounded
__device__ float g_ibasis[NS*64];      // inv DFT [t][ko] tf32-rounded
__device__ float g_ibasisT[64*NS];     // inv DFT [ko][t] tf32-rounded
__device__ float g_whA[2][NM*NC*NC];   // [re/im][k][o][i] tf32-rounded
__device__ float g_wwA[2][NM*NC*NC];
__device__ float g_w1t[8192];          // fc1w tf32 [c][j]
__device__ float g_w2t[8192];          // fc2w tf32 [j][o]
__device__ float g_Xh[(size_t)NB*NC*64*NS];
__device__ float g_Xw[(size_t)NB*NC*64*NS];
__device__ float g_Oh[(size_t)NB*NC*64*NS];
__device__ float g_Ow[(size_t)NB*NC*64*NS];
__device__ float g_f [(size_t)NB*NC*HW];

// ---------------- init ----------------
__global__ void initK(const float* __restrict__ whr, const float* __restrict__ whi,
                      const float* __restrict__ wwr, const float* __restrict__ wwi,
                      const float* __restrict__ fc1w, const float* __restrict__ fc2w) {
    int idx = blockIdx.x * 256 + threadIdx.x;      // covers 131072
    if (idx < NS*64) {
        int t = idx >> 6, ko = idx & 63, k = ko >> 1;
        float s, c;
        sincospif((float)((k * t) & 255) / 128.0f, &s, &c);
        g_basisT[ko*NS + t] = stf((ko & 1) ? -s : c);
        float a = (k == 0) ? (1.0f/NS) : (2.0f/NS);
        float iv = (ko & 1) ? ((k == 0) ? 0.0f : -a*s) : a*c;
        g_ibasis[t*64 + ko]  = stf(iv);
        g_ibasisT[ko*NS + t] = stf(iv);
    }
    if (idx < NM*NC*NC) {
        int k = idx >> 12, r = idx & 4095, o = r >> 6, i = r & 63;
        int src = (i*NC + o)*NM + k;
        g_whA[0][idx] = stf(whr[src]);  g_whA[1][idx] = stf(whi[src]);
        g_wwA[0][idx] = stf(wwr[src]);  g_wwA[1][idx] = stf(wwi[src]);
    }
    if (idx < 8192) {
        g_w1t[idx] = stf(fc1w[idx]);
        g_w2t[idx] = stf(fc2w[idx]);
    }
}

// ---------------- forward DFT over H: Xh[ko][w] = basisT[ko][h] @ x[h][w] ----------------
// smem: sA 64*68 (17408) | sB 64*136 (34816) => 52224
#define FDH_SMEM 52224
__global__ void __launch_bounds__(256) fdftHm(const float* __restrict__ x) {
    extern __shared__ __align__(16) char smem[];
    float* sA = (float*)smem;
    float* sB = (float*)(smem + 17408);
    u32 sAu = s2u(sA), sBu = s2u(sB);
    int slab = blockIdx.x;
    int w0 = blockIdx.y * 128;
    const float* xp = x + (size_t)slab * HW;
    int tid = threadIdx.x, lane = tid & 31, w = tid >> 5;
    int g = lane >> 2, tig = lane & 3;
    int warpM = w & 1, warpN = w >> 1;     // 2 x 4
    float acc[2][4][4] = {};
    for (int hc = 0; hc < NS; hc += 64) {
        for (int i = tid; i < 1024; i += 256) {          // sA: 64x64, 16B chunks
            int ko = i >> 4, c = (i & 15) * 4;
            CP16(sAu + (ko*68 + c)*4, g_basisT + ko*NS + hc + c);
        }
        for (int i = tid; i < 2048; i += 256) {          // sB: 64x128, 16B chunks
            int hh = i >> 5, c = (i & 31) * 4;
            CP16(sBu + (hh*136 + c)*4, xp + (size_t)(hc + hh)*NS + w0 + c);
        }
        CPWAIT();
        __syncthreads();
        #pragma unroll
        for (int ks = 0; ks < 8; ks++) {
            int k0 = ks * 8;
            u32 af[2][4];
            #pragma unroll
            for (int mt = 0; mt < 2; mt++) {
                int r0 = warpM*32 + mt*16;
                af[mt][0] = __float_as_uint(sA[(r0+g)*68 + k0 + tig]);
                af[mt][1] = __float_as_uint(sA[(r0+g+8)*68 + k0 + tig]);
                af[mt][2] = __float_as_uint(sA[(r0+g)*68 + k0 + tig + 4]);
                af[mt][3] = __float_as_uint(sA[(r0+g+8)*68 + k0 + tig + 4]);
            }
            #pragma unroll
            for (int nt = 0; nt < 4; nt++) {
                int n0 = warpN*32 + nt*8;
                u32 bf[2];
                bf[0] = __float_as_uint(sB[(k0+tig)*136 + n0 + g]);
                bf[1] = __float_as_uint(sB[(k0+tig+4)*136 + n0 + g]);
                mma816(acc[0][nt], af[0], bf);
                mma816(acc[1][nt], af[1], bf);
            }
        }
        __syncthreads();
    }
    float* dst = g_Xh + (size_t)slab * 64 * NS;
    #pragma unroll
    for (int mt = 0; mt < 2; mt++) {
        int row = warpM*32 + mt*16 + g;
        #pragma unroll
        for (int nt = 0; nt < 4; nt++) {
            int col = w0 + warpN*32 + nt*8 + 2*tig;
            *(float2*)&dst[row*NS + col]     = make_float2(acc[mt][nt][0], acc[mt][nt][1]);
            *(float2*)&dst[(row+8)*NS + col] = make_float2(acc[mt][nt][2], acc[mt][nt][3]);
        }
    }
}

// ---------------- forward DFT over W: Xw[ko][h] = basisT[ko][w] @ xT[w][h] ----------------
// smem: sA 64*68 (17408) | sB 64*133 (34048) => 51456
#define FDW_SMEM 51456
__global__ void __launch_bounds__(256) fdftWm(const float* __restrict__ x) {
    extern __shared__ __align__(16) char smem[];
    float* sA = (float*)smem;
    float* sB = (float*)(smem + 17408);
    u32 sAu = s2u(sA), sBu = s2u(sB);
    int slab = blockIdx.x;
    int h0 = blockIdx.y * 128;
    const float* xp = x + (size_t)slab * HW;
    int tid = threadIdx.x, lane = tid & 31, w = tid >> 5;
    int g = lane >> 2, tig = lane & 3;
    int warpM = w & 1, warpN = w >> 1;
    float acc[2][4][4] = {};
    for (int wc = 0; wc < NS; wc += 64) {
        for (int i = tid; i < 1024; i += 256) {          // sA: 16B chunks
            int ko = i >> 4, c = (i & 15) * 4;
            CP16(sAu + (ko*68 + c)*4, g_basisT + ko*NS + wc + c);
        }
        for (int i = tid; i < 8192; i += 256) {          // sB transposed: 4B each
            int hh = i >> 6, ww = i & 63;
            CP4(sBu + (ww*133 + hh)*4, xp + (size_t)(h0 + hh)*NS + wc + ww);
        }
        CPWAIT();
        __syncthreads();
        #pragma unroll
        for (int ks = 0; ks < 8; ks++) {
            int k0 = ks * 8;
            u32 af[2][4];
            #pragma unroll
            for (int mt = 0; mt < 2; mt++) {
                int r0 = warpM*32 + mt*16;
                af[mt][0] = __float_as_uint(sA[(r0+g)*68 + k0 + tig]);
                af[mt][1] = __float_as_uint(sA[(r0+g+8)*68 + k0 + tig]);
                af[mt][2] = __float_as_uint(sA[(r0+g)*68 + k0 + tig + 4]);
                af[mt][3] = __float_as_uint(sA[(r0+g+8)*68 + k0 + tig + 4]);
            }
            #pragma unroll
            for (int nt = 0; nt < 4; nt++) {
                int n0 = warpN*32 + nt*8;
                u32 bf[2];
                bf[0] = __float_as_uint(sB[(k0+tig)*133 + n0 + g]);
                bf[1] = __float_as_uint(sB[(k0+tig+4)*133 + n0 + g]);
                mma816(acc[0][nt], af[0], bf);
                mma816(acc[1][nt], af[1], bf);
            }
        }
        __syncthreads();
    }
    float* dst = g_Xw + (size_t)slab * 64 * NS;
    #pragma unroll
    for (int mt = 0; mt < 2; mt++) {
        int row = warpM*32 + mt*16 + g;
        #pragma unroll
        for (int nt = 0; nt < 4; nt++) {
            int col = h0 + warpN*32 + nt*8 + 2*tig;
            *(float2*)&dst[row*NS + col]     = make_float2(acc[mt][nt][0], acc[mt][nt][1]);
            *(float2*)&dst[(row+8)*NS + col] = make_float2(acc[mt][nt][2], acc[mt][nt][3]);
        }
    }
}

// ---------------- per-mode complex mix: O = W @ X (complex), per (b,k), c0 128-wide ----------------
// smem: sWr 64*68 | sWi 64*68 | sXr 64*136 | sXi 64*136 => 104448
#define MIX_SMEM 104448
__global__ void __launch_bounds__(256) mixKm() {
    extern __shared__ __align__(16) char smem[];
    float* sWr = (float*)smem;
    float* sWi = (float*)(smem + 17408);
    float* sXr = (float*)(smem + 34816);
    float* sXi = (float*)(smem + 69632);
    u32 sWru = s2u(sWr), sWiu = s2u(sWi), sXru = s2u(sXr), sXiu = s2u(sXi);
    int br = blockIdx.z;
    const float* Xin = br ? g_Xw : g_Xh;
    const float* Wr  = br ? g_wwA[0] : g_whA[0];
    const float* Wi  = br ? g_wwA[1] : g_whA[1];
    float* Out       = br ? g_Ow : g_Oh;
    int b = blockIdx.x >> 5, k = blockIdx.x & 31;
    int c0 = blockIdx.y * 128;
    int tid = threadIdx.x, lane = tid & 31, w = tid >> 5;
    int g = lane >> 2, tig = lane & 3;
    int warpM = w & 1, warpN = w >> 1;
    for (int i = tid; i < 1024; i += 256) {              // W tiles: 16B chunks
        int o = i >> 4, c = (i & 15) * 4;
        CP16(sWru + (o*68 + c)*4, Wr + k*4096 + o*64 + c);
        CP16(sWiu + (o*68 + c)*4, Wi + k*4096 + o*64 + c);
    }
    for (int i = tid; i < 2048; i += 256) {              // X tiles: 16B chunks
        int ii = i >> 5, c = (i & 31) * 4;
        const float* xb = Xin + ((size_t)(b*64 + ii)*64 + 2*k)*NS + c0;
        CP16(sXru + (ii*136 + c)*4, xb + c);
        CP16(sXiu + (ii*136 + c)*4, xb + NS + c);
    }
    CPWAIT();
    __syncthreads();
    float accR[2][4][4] = {}, accI[2][4][4] = {};
    #pragma unroll
    for (int ks = 0; ks < 8; ks++) {
        int k0 = ks * 8;
        u32 ar[2][4], ai[2][4], nai[2][4];
        #pragma unroll
        for (int mt = 0; mt < 2; mt++) {
            int r0 = warpM*32 + mt*16;
            ar[mt][0] = __float_as_uint(sWr[(r0+g)*68 + k0 + tig]);
            ar[mt][1] = __float_as_uint(sWr[(r0+g+8)*68 + k0 + tig]);
            ar[mt][2] = __float_as_uint(sWr[(r0+g)*68 + k0 + tig + 4]);
            ar[mt][3] = __float_as_uint(sWr[(r0+g+8)*68 + k0 + tig + 4]);
            ai[mt][0] = __float_as_uint(sWi[(r0+g)*68 + k0 + tig]);
            ai[mt][1] = __float_as_uint(sWi[(r0+g+8)*68 + k0 + tig]);
            ai[mt][2] = __float_as_uint(sWi[(r0+g)*68 + k0 + tig + 4]);
            ai[mt][3] = __float_as_uint(sWi[(r0+g+8)*68 + k0 + tig + 4]);
            #pragma unroll
            for (int j = 0; j < 4; j++) nai[mt][j] = ai[mt][j] ^ 0x80000000u;
        }
        #pragma unroll
        for (int nt = 0; nt < 4; nt++) {
            int n0 = warpN*32 + nt*8;
            u32 bfr[2], bfi[2];
            bfr[0] = __float_as_uint(sXr[(k0+tig)*136 + n0 + g]);
            bfr[1] = __float_as_uint(sXr[(k0+tig+4)*136 + n0 + g]);
            bfi[0] = __float_as_uint(sXi[(k0+tig)*136 + n0 + g]);
            bfi[1] = __float_as_uint(sXi[(k0+tig+4)*136 + n0 + g]);
            #pragma unroll
            for (int mt = 0; mt < 2; mt++) {
                mma816(accR[mt][nt], ar[mt], bfr);
                mma816(accR[mt][nt], nai[mt], bfi);
                mma816(accI[mt][nt], ar[mt], bfi);
                mma816(accI[mt][nt], ai[mt], bfr);
            }
        }
    }
    #pragma unroll
    for (int mt = 0; mt < 2; mt++) {
        #pragma unroll
        for (int nt = 0; nt < 4; nt++) {
            int col = c0 + warpN*32 + nt*8 + 2*tig;
            int o0 = warpM*32 + mt*16 + g;
            float* ob0 = Out + ((size_t)(b*64 + o0)*64 + 2*k)*NS + col;
            *(float2*)ob0        = make_float2(accR[mt][nt][0], accR[mt][nt][1]);
            *(float2*)(ob0 + NS) = make_float2(accI[mt][nt][0], accI[mt][nt][1]);
            float* ob1 = Out + ((size_t)(b*64 + o0 + 8)*64 + 2*k)*NS + col;
            *(float2*)ob1        = make_float2(accR[mt][nt][2], accR[mt][nt][3]);
            *(float2*)(ob1 + NS) = make_float2(accI[mt][nt][2], accI[mt][nt][3]);
        }
    }
}

// ---------------- fused inverse DFTs: f = IBh@Oh + OwT@IBw, 128x64 tiles ----------------
// smem: sAh 128*68 (34816) | sAw 128*69 (35328) | sBh 64*72 (18432) | sBw 64*72 (18432) => 107008
#define INV_SMEM 107008
__global__ void __launch_bounds__(256) invHWm() {
    extern __shared__ __align__(16) char smem[];
    float* sAh = (float*)smem;
    float* sAw = (float*)(smem + 34816);
    float* sBh = (float*)(smem + 70144);
    float* sBw = (float*)(smem + 88576);
    u32 sAhu = s2u(sAh), sAwu = s2u(sAw), sBhu = s2u(sBh), sBwu = s2u(sBw);
    int slab = blockIdx.x;
    int h0 = (blockIdx.y >> 2) * 128, w0 = (blockIdx.y & 3) * 64;
    const float* Oh = g_Oh + (size_t)slab * 64 * NS;
    const float* Ow = g_Ow + (size_t)slab * 64 * NS;
    int tid = threadIdx.x, lane = tid & 31, w = tid >> 5;
    int g = lane >> 2, tig = lane & 3;
    int warpM = w >> 1, warpN = w & 1;     // 4 x 2
    for (int i = tid; i < 2048; i += 256) {              // sAh: 128x64, 16B chunks
        int r = i >> 4, c = (i & 15) * 4;
        CP16(sAhu + (r*68 + c)*4, g_ibasis + (h0 + r)*64 + c);
    }
    for (int i = tid; i < 8192; i += 256) {              // sAw transposed: 4B each
        int ko = i >> 7, hh = i & 127;
        CP4(sAwu + (hh*69 + ko)*4, Ow + ko*NS + h0 + hh);
    }
    for (int i = tid; i < 1024; i += 256) {              // sBh/sBw: 16B chunks
        int ko = i >> 4, c = (i & 15) * 4;
        CP16(sBhu + (ko*72 + c)*4, Oh + ko*NS + w0 + c);
        CP16(sBwu + (ko*72 + c)*4, g_ibasisT + ko*NS + w0 + c);
    }
    CPWAIT();
    __syncthreads();
    float acc[2][4][4] = {};
    #pragma unroll
    for (int ks = 0; ks < 8; ks++) {
        int k0 = ks * 8;
        u32 ah[2][4], aw[2][4];
        #pragma unroll
        for (int mt = 0; mt < 2; mt++) {
            int r0 = warpM*32 + mt*16;
            ah[mt][0] = __float_as_uint(sAh[(r0+g)*68 + k0 + tig]);
            ah[mt][1] = __float_as_uint(sAh[(r0+g+8)*68 + k0 + tig]);
            ah[mt][2] = __float_as_uint(sAh[(r0+g)*68 + k0 + tig + 4]);
            ah[mt][3] = __float_as_uint(sAh[(r0+g+8)*68 + k0 + tig + 4]);
            aw[mt][0] = __float_as_uint(sAw[(r0+g)*69 + k0 + tig]);
            aw[mt][1] = __float_as_uint(sAw[(r0+g+8)*69 + k0 + tig]);
            aw[mt][2] = __float_as_uint(sAw[(r0+g)*69 + k0 + tig + 4]);
            aw[mt][3] = __float_as_uint(sAw[(r0+g+8)*69 + k0 + tig + 4]);
        }
        #pragma unroll
        for (int nt = 0; nt < 4; nt++) {
            int n0 = warpN*32 + nt*8;
            u32 bh[2], bw[2];
            bh[0] = __float_as_uint(sBh[(k0+tig)*72 + n0 + g]);
            bh[1] = __float_as_uint(sBh[(k0+tig+4)*72 + n0 + g]);
            bw[0] = __float_as_uint(sBw[(k0+tig)*72 + n0 + g]);
            bw[1] = __float_as_uint(sBw[(k0+tig+4)*72 + n0 + g]);
            #pragma unroll
            for (int mt = 0; mt < 2; mt++) {
                mma816(acc[mt][nt], ah[mt], bh);
                mma816(acc[mt][nt], aw[mt], bw);
            }
        }
    }
    __syncthreads();   // sAh dead; reuse as output staging [128][68]
    #pragma unroll
    for (int mt = 0; mt < 2; mt++) {
        int r0 = warpM*32 + mt*16 + g;
        #pragma unroll
        for (int nt = 0; nt < 4; nt++) {
            int col = warpN*32 + nt*8 + 2*tig;
            *(float2*)&sAh[r0*68 + col]     = make_float2(acc[mt][nt][0], acc[mt][nt][1]);
            *(float2*)&sAh[(r0+8)*68 + col] = make_float2(acc[mt][nt][2], acc[mt][nt][3]);
        }
    }
    __syncthreads();
    float* fp = g_f + (size_t)slab * HW;
    for (int idx = tid; idx < 8192; idx += 256) {
        int r = idx >> 6, c = idx & 63;
        fp[(size_t)(h0 + r)*NS + w0 + c] = sAh[r*68 + c];
    }
}

// ---------------- mma.sync tf32 FFN: 128 px / block, 512 threads, aliased smem (unchanged) ----------------
#define FFN_SMEM 106496
#define OFF_T1 2048
#define OFF_WB 69632

__global__ void __launch_bounds__(512) ffnM(const float* __restrict__ x,
        const float* __restrict__ b1, const float* __restrict__ lng,
        const float* __restrict__ lnb, const float* __restrict__ b2,
        float* __restrict__ out) {
    extern __shared__ __align__(16) char smem[];
    float* sVec = (float*)smem;
    float* sT = (float*)(smem + OFF_T1);
    float* sA = sT;
    float* sW = (float*)(smem + OFF_WB);
    int tid = threadIdx.x, lane = tid & 31, w = tid >> 5;
    int b  = blockIdx.x >> 9;
    int p0 = (blockIdx.x & 511) * 128;

    if (tid < 128) { sVec[tid] = b1[tid]; sVec[128+tid] = lng[tid]; sVec[256+tid] = lnb[tid]; }
    if (tid < 64) sVec[384+tid] = b2[tid];
    for (int i = tid; i < 2048; i += 512) {
        int c = i >> 5, j4 = (i & 31) * 4;
        *(float4*)&sW[c*136 + j4] = ((const float4*)g_w1t)[i];
    }
    for (int i = tid; i < 8192; i += 512) {
        int c = i >> 7, px = i & 127;
        sA[px*68 + c] = stf(g_f[((size_t)(b*64 + c) << 16) + p0 + px]);
    }
    __syncthreads();

    int warpM = w & 3, warpN = w >> 2;
    int g = lane >> 2, tig = lane & 3;

    float acc[2][4][4] = {};
    #pragma unroll
    for (int ks = 0; ks < 8; ks++) {
        int k0 = ks * 8;
        u32 afr[2][4];
        #pragma unroll
        for (int mt = 0; mt < 2; mt++) {
            const float* ap = sA + (warpM*32 + mt*16)*68 + k0;
            afr[mt][0] = __float_as_uint(ap[g*68 + tig]);
            afr[mt][1] = __float_as_uint(ap[(g+8)*68 + tig]);
            afr[mt][2] = __float_as_uint(ap[g*68 + tig + 4]);
            afr[mt][3] = __float_as_uint(ap[(g+8)*68 + tig + 4]);
        }
        #pragma unroll
        for (int nt = 0; nt < 4; nt++) {
            const float* bp = sW + k0*136 + warpN*32 + nt*8;
            u32 bfr[2];
            bfr[0] = __float_as_uint(bp[tig*136 + g]);
            bfr[1] = __float_as_uint(bp[(tig+4)*136 + g]);
            mma816(acc[0][nt], afr[0], bfr);
            mma816(acc[1][nt], afr[1], bfr);
        }
    }
    __syncthreads();
    #pragma unroll
    for (int mt = 0; mt < 2; mt++) {
        int r0 = warpM*32 + mt*16 + g;
        #pragma unroll
        for (int nt = 0; nt < 4; nt++) {
            int cb = warpN*32 + nt*8 + 2*tig;
            float bb0 = sVec[cb], bb1 = sVec[cb+1];
            sT[r0*132 + cb]     = fmaxf(acc[mt][nt][0] + bb0, 0.f);
            sT[r0*132 + cb + 1] = fmaxf(acc[mt][nt][1] + bb1, 0.f);
            sT[(r0+8)*132 + cb]     = fmaxf(acc[mt][nt][2] + bb0, 0.f);
            sT[(r0+8)*132 + cb + 1] = fmaxf(acc[mt][nt][3] + bb1, 0.f);
        }
    }
    __syncthreads();

    for (int p8 = 0; p8 < 8; p8++) {
        int px = w*8 + p8;
        float4 v = *(float4*)&sT[px*132 + lane*4];
        float s1 = v.x + v.y + v.z + v.w;
        float s2 = v.x*v.x + v.y*v.y + v.z*v.z + v.w*v.w;
        #pragma unroll
        for (int o = 16; o > 0; o >>= 1) {
            s1 += __shfl_xor_sync(0xFFFFFFFFu, s1, o);
            s2 += __shfl_xor_sync(0xFFFFFFFFu, s2, o);
        }
        float mu  = s1 * (1.0f/128.0f);
        float var = s2 * (1.0f/128.0f) - mu*mu;
        float inv = rsqrtf(var + 1e-5f);
        float4 gm = *(float4*)&sVec[128 + lane*4];
        float4 bt = *(float4*)&sVec[256 + lane*4];
        uint4 q;
        q.x = tf32b((v.x - mu)*inv*gm.x + bt.x);
        q.y = tf32b((v.y - mu)*inv*gm.y + bt.y);
        q.z = tf32b((v.z - mu)*inv*gm.z + bt.z);
        q.w = tf32b((v.w - mu)*inv*gm.w + bt.w);
        *(uint4*)&sT[px*132 + lane*4] = q;
    }
    __syncthreads();

    for (int i = tid; i < 2048; i += 512) {
        int j = i >> 4, o4 = (i & 15) * 4;
        *(float4*)&sW[j*72 + o4] = ((const float4*)g_w2t)[i];
    }
    __syncthreads();

    float acc2[2][2][4] = {};
    #pragma unroll
    for (int ks = 0; ks < 16; ks++) {
        int k0 = ks * 8;
        u32 afr[2][4];
        #pragma unroll
        for (int mt = 0; mt < 2; mt++) {
            const float* ap = sT + (warpM*32 + mt*16)*132 + k0;
            afr[mt][0] = __float_as_uint(ap[g*132 + tig]);
            afr[mt][1] = __float_as_uint(ap[(g+8)*132 + tig]);
            afr[mt][2] = __float_as_uint(ap[g*132 + tig + 4]);
            afr[mt][3] = __float_as_uint(ap[(g+8)*132 + tig + 4]);
        }
        #pragma unroll
        for (int nt = 0; nt < 2; nt++) {
            const float* bp = sW + k0*72 + warpN*16 + nt*8;
            u32 bfr[2];
            bfr[0] = __float_as_uint(bp[tig*72 + g]);
            bfr[1] = __float_as_uint(bp[(tig+4)*72 + g]);
            mma816(acc2[0][nt], afr[0], bfr);
            mma816(acc2[1][nt], afr[1], bfr);
        }
    }
    __syncthreads();
    float* sO = sW;
    #pragma unroll
    for (int mt = 0; mt < 2; mt++) {
        int r0 = warpM*32 + mt*16 + g;
        #pragma unroll
        for (int nt = 0; nt < 2; nt++) {
            int ob = warpN*16 + nt*8 + 2*tig;
            float bb0 = sVec[384 + ob], bb1 = sVec[384 + ob + 1];
            sO[ob*132 + r0]       = acc2[mt][nt][0] + bb0;
            sO[(ob+1)*132 + r0]   = acc2[mt][nt][1] + bb1;
            sO[ob*132 + r0 + 8]   = acc2[mt][nt][2] + bb0;
            sO[(ob+1)*132 + r0+8] = acc2[mt][nt][3] + bb1;
        }
    }
    __syncthreads();
    for (int i = tid; i < 8192; i += 512) {
        int o = i >> 7, px = i & 127;
        size_t gg = ((size_t)(b*64 + o) << 16) + p0 + px;
        out[gg] = sO[o*132 + px] + x[gg];
    }
}

// ---------------- launch ----------------
extern "C" void kernel_launch(void* const* d_in, const int* in_sizes, int n_in,
                              void* d_out, int out_size) {
    const float* x    = (const float*)d_in[0];
    const float* whr  = (const float*)d_in[1];
    const float* whi  = (const float*)d_in[2];
    const float* wwr  = (const float*)d_in[3];
    const float* wwi  = (const float*)d_in[4];
    const float* fc1w = (const float*)d_in[5];
    const float* fc1b = (const float*)d_in[6];
    const float* lng  = (const float*)d_in[7];
    const float* lnb  = (const float*)d_in[8];
    const float* fc2w = (const float*)d_in[9];
    const float* fc2b = (const float*)d_in[10];
    float* out = (float*)d_out;

    cudaFuncSetAttribute(fdftHm, cudaFuncAttributeMaxDynamicSharedMemorySize, FDH_SMEM);
    cudaFuncSetAttribute(fdftWm, cudaFuncAttributeMaxDynamicSharedMemorySize, FDW_SMEM);
    cudaFuncSetAttribute(mixKm,  cudaFuncAttributeMaxDynamicSharedMemorySize, MIX_SMEM);
    cudaFuncSetAttribute(invHWm, cudaFuncAttributeMaxDynamicSharedMemorySize, INV_SMEM);
    cudaFuncSetAttribute(ffnM,   cudaFuncAttributeMaxDynamicSharedMemorySize, FFN_SMEM);

    initK<<<512, 256>>>(whr, whi, wwr, wwi, fc1w, fc2w);
    fdftHm<<<dim3(512, 2), 256, FDH_SMEM>>>(x);
    fdftWm<<<dim3(512, 2), 256, FDW_SMEM>>>(x);
    mixKm<<<dim3(256, 2, 2), 256, MIX_SMEM>>>();
    invHWm<<<dim3(512, 8), 256, INV_SMEM>>>();
    ffnM<<<4096, 512, FFN_SMEM>>>(x, fc1b, lng, lnb, fc2b, out);
}